// round 3
// baseline (speedup 1.0000x reference)
#include <cuda_runtime.h>
#include <math.h>
#include <stdio.h>

// ---------------- static problem capacities ----------------
#define MAXN 50000
#define MAXE 800000
#define HCn  256      // H*C
#define Hh   4
#define Cc   64
#define NG   64       // graphs
#define NA   32       // actions

// ---------------- device scratch (allocation-free rule) ----------------
__device__ float g_h  [(size_t)MAXN * HCn];   // projection buffer (reused both layers)
__device__ float g_agg[(size_t)MAXN * HCn];   // aggregation buffer (reused both layers)
__device__ float g_h2 [(size_t)MAXN * HCn];   // layer-2 input = elu(agg1/den + b1)
__device__ float g_asrc[MAXN * Hh];
__device__ float g_adst[MAXN * Hh];
__device__ float g_m   [MAXN * Hh];
__device__ float g_den [MAXN * Hh];
__device__ float g_hf  [(size_t)MAXN * Cc];   // final node features [N,64]
__device__ float g_pooled[NG * Cc];
__device__ int   g_start[NG];
__device__ int   g_end  [NG];

// ---------------- helpers ----------------
__device__ __forceinline__ float lrelu(float x) { return fmaxf(x, 0.2f * x); }
__device__ __forceinline__ float elu1(float x)  { return x > 0.f ? x : expm1f(x); }

__device__ __forceinline__ void atomicMaxF(float* a, float v) {
    if (v >= 0.f) atomicMax((int*)a, __float_as_int(v));
    else          atomicMin((unsigned int*)a, __float_as_uint(v));
}

__device__ __forceinline__ void red_add_v4(float* a, float4 v) {
    asm volatile("red.global.add.v4.f32 [%0], {%1,%2,%3,%4};"
                 :: "l"(a), "f"(v.x), "f"(v.y), "f"(v.z), "f"(v.w) : "memory");
}

// ---------------- generic fill ----------------
__global__ void fill_f32(float* p, size_t n, float v) {
    size_t i = (size_t)blockIdx.x * blockDim.x + threadIdx.x;
    if (i < n) p[i] = v;
}

__global__ void init_bounds_k(int* start, int* end) {
    int i = threadIdx.x;
    if (i < NG) { start[i] = 1 << 30; end[i] = 0; }
}

// ---------------- tiled fp32 GEMM: C[M,256] = A[M,K] @ B[K,256] ----------------
#define BM 128
#define BN 64
#define BK 16
#define TM 8
#define TN 4
__global__ __launch_bounds__(256) void gemm_tiled(
    const float* __restrict__ A, const float* __restrict__ B,
    float* __restrict__ Cmat, int M, int K, int N)
{
    __shared__ float As[BK][BM];
    __shared__ float Bs[BK][BN];
    const int tid = threadIdx.x;
    const int tx = tid & 15;        // 0..15 -> N
    const int ty = tid >> 4;        // 0..15 -> M
    const int block_row = blockIdx.y * BM;
    const int block_col = blockIdx.x * BN;

    float acc[TM][TN];
#pragma unroll
    for (int m = 0; m < TM; m++)
#pragma unroll
        for (int n = 0; n < TN; n++) acc[m][n] = 0.f;

    for (int k0 = 0; k0 < K; k0 += BK) {
#pragma unroll
        for (int i = 0; i < 2; i++) {
            int idx = tid * 2 + i;            // 0..511
            int m   = idx >> 2;               // 0..127
            int kg  = (idx & 3) * 4;          // 0,4,8,12
            int grow = block_row + m;
            float4 v = make_float4(0.f, 0.f, 0.f, 0.f);
            if (grow < M) v = *(const float4*)&A[(size_t)grow * K + k0 + kg];
            As[kg + 0][m] = v.x; As[kg + 1][m] = v.y;
            As[kg + 2][m] = v.z; As[kg + 3][m] = v.w;
        }
        {
            int kr = tid >> 4;                // 0..15
            int ng = (tid & 15) * 4;          // 0..60
            float4 v = *(const float4*)&B[(size_t)(k0 + kr) * N + block_col + ng];
            *(float4*)&Bs[kr][ng] = v;
        }
        __syncthreads();
#pragma unroll
        for (int kk = 0; kk < BK; kk++) {
            float a[TM], b[TN];
#pragma unroll
            for (int m = 0; m < TM; m++) a[m] = As[kk][ty * TM + m];
#pragma unroll
            for (int n = 0; n < TN; n++) b[n] = Bs[kk][tx * TN + n];
#pragma unroll
            for (int m = 0; m < TM; m++)
#pragma unroll
                for (int n = 0; n < TN; n++) acc[m][n] = fmaf(a[m], b[n], acc[m][n]);
        }
        __syncthreads();
    }
#pragma unroll
    for (int m = 0; m < TM; m++) {
        int grow = block_row + ty * TM + m;
        if (grow < M) {
            float4 v = make_float4(acc[m][0], acc[m][1], acc[m][2], acc[m][3]);
            *(float4*)&Cmat[(size_t)grow * N + block_col + tx * TN] = v;
        }
    }
}

// ---------------- attention scores ----------------
__global__ __launch_bounds__(256) void attn_scores(
    const float* __restrict__ h, const float* __restrict__ att_src,
    const float* __restrict__ att_dst, float* __restrict__ a_src,
    float* __restrict__ a_dst, int N)
{
    __shared__ float s_src[HCn], s_dst[HCn];
    int tid = threadIdx.x;
    s_src[tid] = att_src[tid];
    s_dst[tid] = att_dst[tid];
    __syncthreads();
    int warp = (int)((blockIdx.x * (size_t)blockDim.x + tid) >> 5);
    int lane = tid & 31;
    if (warp >= N) return;
    float ss = 0.f, sd = 0.f;
    const float4* hp = (const float4*)&h[(size_t)warp * HCn + lane * 8];
    const float4* sp = (const float4*)&s_src[lane * 8];
    const float4* dp = (const float4*)&s_dst[lane * 8];
#pragma unroll
    for (int j = 0; j < 2; j++) {
        float4 hv = hp[j], as = sp[j], ad = dp[j];
        ss += hv.x * as.x + hv.y * as.y + hv.z * as.z + hv.w * as.w;
        sd += hv.x * ad.x + hv.y * ad.y + hv.z * ad.z + hv.w * ad.w;
    }
#pragma unroll
    for (int o = 4; o; o >>= 1) {
        ss += __shfl_xor_sync(0xffffffffu, ss, o);
        sd += __shfl_xor_sync(0xffffffffu, sd, o);
    }
    if ((lane & 7) == 0) {
        int head = lane >> 3;
        a_src[warp * Hh + head] = ss;
        a_dst[warp * Hh + head] = sd;
    }
}

// ---------------- edge pass 1: per-dst max of leaky(e) ----------------
__global__ __launch_bounds__(256) void edge_max_k(
    const int* __restrict__ ei, int E, int N,
    const float* __restrict__ a_src, const float* __restrict__ a_dst,
    float* __restrict__ m)
{
    int i = blockIdx.x * blockDim.x + threadIdx.x;
    int ET = E + N;
    if (i >= ET) return;
    int s, d;
    if (i < E) { s = ei[i]; d = ei[E + i]; }
    else       { s = d = i - E; }
    if ((unsigned)s >= (unsigned)N || (unsigned)d >= (unsigned)N) return;
    float4 as = *(const float4*)&a_src[s * Hh];
    float4 ad = *(const float4*)&a_dst[d * Hh];
    atomicMaxF(&m[d * Hh + 0], lrelu(as.x + ad.x));
    atomicMaxF(&m[d * Hh + 1], lrelu(as.y + ad.y));
    atomicMaxF(&m[d * Hh + 2], lrelu(as.z + ad.z));
    atomicMaxF(&m[d * Hh + 3], lrelu(as.w + ad.w));
}

// ---------------- edge pass 2: denom ----------------
__global__ __launch_bounds__(256) void edge_den_k(
    const int* __restrict__ ei, int E, int N,
    const float* __restrict__ a_src, const float* __restrict__ a_dst,
    const float* __restrict__ m, float* __restrict__ den)
{
    int i = blockIdx.x * blockDim.x + threadIdx.x;
    int ET = E + N;
    if (i >= ET) return;
    int s, d;
    if (i < E) { s = ei[i]; d = ei[E + i]; }
    else       { s = d = i - E; }
    if ((unsigned)s >= (unsigned)N || (unsigned)d >= (unsigned)N) return;
    float4 as = *(const float4*)&a_src[s * Hh];
    float4 ad = *(const float4*)&a_dst[d * Hh];
    float4 mm = *(const float4*)&m[d * Hh];
    atomicAdd(&den[d * Hh + 0], expf(lrelu(as.x + ad.x) - mm.x));
    atomicAdd(&den[d * Hh + 1], expf(lrelu(as.y + ad.y) - mm.y));
    atomicAdd(&den[d * Hh + 2], expf(lrelu(as.z + ad.z) - mm.z));
    atomicAdd(&den[d * Hh + 3], expf(lrelu(as.w + ad.w) - mm.w));
}

// ---------------- edge pass 3: agg[dst] += p * h[src] (unnormalized) ----------------
__global__ __launch_bounds__(256) void edge_agg_k(
    const int* __restrict__ ei, int E, int N,
    const float* __restrict__ a_src, const float* __restrict__ a_dst,
    const float* __restrict__ m,
    const float* __restrict__ h, float* __restrict__ agg)
{
    int gw = (int)(((size_t)blockIdx.x * blockDim.x + threadIdx.x) >> 5);
    int lane = threadIdx.x & 31;
    int ET = E + N;
    if (gw >= ET) return;
    int s = 0, d = 0;
    if (lane == 0) {
        if (gw < E) { s = ei[gw]; d = ei[E + gw]; }
        else        { s = d = gw - E; }
    }
    s = __shfl_sync(0xffffffffu, s, 0);
    d = __shfl_sync(0xffffffffu, d, 0);
    if ((unsigned)s >= (unsigned)N || (unsigned)d >= (unsigned)N) return;
    int head = lane >> 3;
    float e = lrelu(a_src[s * Hh + head] + a_dst[d * Hh + head]);
    float p = expf(e - m[d * Hh + head]);
    const float4* hp = (const float4*)&h[(size_t)s * HCn + lane * 8];
    float4 v0 = hp[0], v1 = hp[1];
    v0.x *= p; v0.y *= p; v0.z *= p; v0.w *= p;
    v1.x *= p; v1.y *= p; v1.z *= p; v1.w *= p;
    float* dst0 = &agg[(size_t)d * HCn + lane * 8];
    red_add_v4(dst0, v0);
    red_add_v4(dst0 + 4, v1);
}

// ---------------- layer-1 epilogue: h2 = elu(agg/den + b1) ----------------
__global__ __launch_bounds__(256) void finalize1_k(
    const float* __restrict__ agg, const float* __restrict__ den,
    const float* __restrict__ b1, float* __restrict__ h2, int N)
{
    size_t i = (size_t)blockIdx.x * blockDim.x + threadIdx.x;
    if (i >= (size_t)N * HCn) return;
    int c256 = (int)(i & (HCn - 1));
    int n = (int)(i >> 8);
    int head = c256 >> 6;
    float v = agg[i] / den[n * Hh + head] + b1[c256];
    h2[i] = elu1(v);
}

// ---------------- layer-2 epilogue: hf = elu(mean_h(agg/den) + b2) ----------------
__global__ __launch_bounds__(256) void finalize2_k(
    const float* __restrict__ agg, const float* __restrict__ den,
    const float* __restrict__ b2, float* __restrict__ hf, int N)
{
    size_t i = (size_t)blockIdx.x * blockDim.x + threadIdx.x;
    if (i >= (size_t)N * Cc) return;
    int c = (int)(i & (Cc - 1));
    int n = (int)(i >> 6);
    const float* ar = &agg[(size_t)n * HCn];
    const float* dr = &den[n * Hh];
    float v = 0.f;
#pragma unroll
    for (int hd = 0; hd < Hh; hd++) v += ar[hd * Cc + c] / dr[hd];
    v = v * 0.25f + b2[c];
    hf[i] = elu1(v);
}

// ---------------- pooling ----------------
__global__ void graph_bounds_k(const int* __restrict__ batch, int N,
                               int* __restrict__ start, int* __restrict__ end)
{
    int n = blockIdx.x * blockDim.x + threadIdx.x;
    if (n >= N) return;
    int g = batch[n];
    if (g < 0 || g >= NG) return;
    atomicMin(&start[g], n);
    atomicMax(&end[g], n + 1);
}

__global__ __launch_bounds__(256) void pool_k(
    const float* __restrict__ hf, const int* __restrict__ start,
    const int* __restrict__ end, float* __restrict__ pooled)
{
    int g = blockIdx.x;
    int tid = threadIdx.x;
    int col = tid & 63, sub = tid >> 6;   // 4 sub-accumulators
    int s = start[g], e = end[g];
    if (s > e) { s = 0; e = 0; }
    float acc = 0.f;
    for (int n = s + sub; n < e; n += 4) acc += hf[(size_t)n * Cc + col];
    __shared__ float sm[256];
    sm[tid] = acc;
    __syncthreads();
    if (sub == 0) {
        float v = sm[col] + sm[64 + col] + sm[128 + col] + sm[192 + col];
        float cnt = (e > s) ? (float)(e - s) : 0.f;
        pooled[g * Cc + col] = v / fmaxf(cnt, 1.0f);
    }
}

// ---------------- final head: out[64,32] = pooled @ Wa + ba ----------------
__global__ __launch_bounds__(1024) void head_k(
    const float* __restrict__ pooled, const float* __restrict__ Wa,
    const float* __restrict__ ba, float* __restrict__ out)
{
    __shared__ float sW[Cc * NA];
    int t = threadIdx.y * 32 + threadIdx.x;
    for (int i = t; i < Cc * NA; i += 1024) sW[i] = Wa[i];
    __syncthreads();
    int a = threadIdx.x;  // 0..31
#pragma unroll
    for (int rep = 0; rep < 2; rep++) {
        int g = threadIdx.y + rep * 32;
        float acc = ba[a];
#pragma unroll 8
        for (int c = 0; c < Cc; c++) acc = fmaf(pooled[g * Cc + c], sW[c * NA + a], acc);
        out[g * NA + a] = acc;
    }
}

// ---------------- host orchestration ----------------
static float* symf(const void* sym) {
    void* p = nullptr;
    cudaGetSymbolAddress(&p, sym);
    return (float*)p;
}
static int* symi(const void* sym) {
    void* p = nullptr;
    cudaGetSymbolAddress(&p, sym);
    return (int*)p;
}

static void run_gat_layer(const float* in, int M, int K,
                          const float* W, const float* att_s, const float* att_d,
                          const int* ei, int E, int N,
                          float* h, float* agg, float* asrc, float* adst,
                          float* m, float* den)
{
    dim3 gg(HCn / BN, (M + BM - 1) / BM);
    gemm_tiled<<<gg, 256>>>(in, W, h, M, K, HCn);
    {
        size_t threads = (size_t)N * 32;
        attn_scores<<<(unsigned)((threads + 255) / 256), 256>>>(h, att_s, att_d, asrc, adst, N);
    }
    fill_f32<<<(unsigned)(((size_t)N * Hh + 255) / 256), 256>>>(m, (size_t)N * Hh, -INFINITY);
    fill_f32<<<(unsigned)(((size_t)N * Hh + 255) / 256), 256>>>(den, (size_t)N * Hh, 0.f);
    fill_f32<<<(unsigned)(((size_t)N * HCn + 255) / 256), 256>>>(agg, (size_t)N * HCn, 0.f);
    int ET = E + N;
    edge_max_k<<<(ET + 255) / 256, 256>>>(ei, E, N, asrc, adst, m);
    edge_den_k<<<(ET + 255) / 256, 256>>>(ei, E, N, asrc, adst, m, den);
    {
        size_t threads = (size_t)ET * 32;
        edge_agg_k<<<(unsigned)((threads + 255) / 256), 256>>>(ei, E, N, asrc, adst, m, h, agg);
    }
}

extern "C" void kernel_launch(void* const* d_in, const int* in_sizes, int n_in,
                              void* d_out, int out_size)
{
    // -------- robust input mapping (filter size-1 scalar inputs) --------
    const void* t[13];
    int tsz[13];
    int cnt = 0;
    for (int i = 0; i < n_in && cnt < 13; i++) {
        if (in_sizes[i] <= 1) continue;   // skip num_wires / num_terminals scalars
        t[cnt] = d_in[i];
        tsz[cnt] = in_sizes[i];
        cnt++;
    }
    if (cnt < 13) return;

    const float* x     = (const float*)t[0];
    const int*   ei    = (const int*)t[1];     // int32 (JAX x64 disabled)
    const int*   batch = (const int*)t[2];     // int32
    const float* W1    = (const float*)t[3];
    const float* attS1 = (const float*)t[4];
    const float* attD1 = (const float*)t[5];
    const float* b1    = (const float*)t[6];
    const float* W2    = (const float*)t[7];
    const float* attS2 = (const float*)t[8];
    const float* attD2 = (const float*)t[9];
    const float* b2    = (const float*)t[10];
    const float* Wa    = (const float*)t[11];
    const float* ba    = (const float*)t[12];

    const int Fin = 128;
    int N = tsz[0] / Fin;
    int E = tsz[1] / 2;
    if (N > MAXN || E > MAXE || N <= 0 || E <= 0) return;

    float* h    = symf(g_h);
    float* agg  = symf(g_agg);
    float* h2   = symf(g_h2);
    float* asrc = symf(g_asrc);
    float* adst = symf(g_adst);
    float* m    = symf(g_m);
    float* den  = symf(g_den);
    float* hf   = symf(g_hf);
    float* pooled = symf(g_pooled);
    int* gstart = symi(g_start);
    int* gend   = symi(g_end);

    // ---- layer 1 ----
    run_gat_layer(x, N, Fin, W1, attS1, attD1, ei, E, N, h, agg, asrc, adst, m, den);
    finalize1_k<<<(unsigned)(((size_t)N * HCn + 255) / 256), 256>>>(agg, den, b1, h2, N);

    // ---- layer 2 ----
    run_gat_layer(h2, N, HCn, W2, attS2, attD2, ei, E, N, h, agg, asrc, adst, m, den);
    finalize2_k<<<(unsigned)(((size_t)N * Cc + 255) / 256), 256>>>(agg, den, b2, hf, N);

    // ---- pooling ----
    init_bounds_k<<<1, 64>>>(gstart, gend);
    fill_f32<<<(NG * Cc + 255) / 256, 256>>>(pooled, NG * Cc, 0.f);
    graph_bounds_k<<<(N + 255) / 256, 256>>>(batch, N, gstart, gend);
    pool_k<<<NG, 256>>>(hf, gstart, gend, pooled);

    // ---- head ----
    head_k<<<1, dim3(32, 32)>>>(pooled, Wa, ba, (float*)d_out);
}

// round 4
// speedup vs baseline: 1.1667x; 1.1667x over previous
#include <cuda_runtime.h>
#include <math.h>
#include <stdio.h>
#include <stdint.h>

// ---------------- static problem capacities ----------------
#define MAXN 50000
#define MAXE 800000
#define HCn  256      // H*C
#define Hh   4
#define Cc   64
#define NG   64       // graphs
#define NA   32       // actions

// ---------------- device scratch (allocation-free rule) ----------------
__device__ float g_h  [(size_t)MAXN * HCn];   // projection buffer (reused both layers)
__device__ float g_agg[(size_t)MAXN * HCn];   // aggregation buffer (reused both layers)
__device__ float g_h2 [(size_t)MAXN * HCn];   // layer-2 input
__device__ float g_asrc[MAXN * Hh];
__device__ float g_adst[MAXN * Hh];
__device__ float g_m   [MAXN * Hh];
__device__ float g_den [MAXN * Hh];
__device__ float g_hf  [(size_t)MAXN * Cc];   // final node features [N,64]
__device__ float g_pooled[NG * Cc];
__device__ int   g_start[NG];
__device__ int   g_end  [NG];

// ---------------- helpers ----------------
__device__ __forceinline__ float lrelu(float x) { return fmaxf(x, 0.2f * x); }
__device__ __forceinline__ float elu1(float x)  { return x > 0.f ? x : expm1f(x); }

__device__ __forceinline__ void atomicMaxF(float* a, float v) {
    if (v >= 0.f) atomicMax((int*)a, __float_as_int(v));
    else          atomicMin((unsigned int*)a, __float_as_uint(v));
}

__device__ __forceinline__ void red_add_v4(float* a, float4 v) {
    asm volatile("red.global.add.v4.f32 [%0], {%1,%2,%3,%4};"
                 :: "l"(a), "f"(v.x), "f"(v.y), "f"(v.z), "f"(v.w) : "memory");
}

__device__ __forceinline__ uint32_t f2tf(float f) {
    uint32_t r;
    asm("cvt.rna.tf32.f32 %0, %1;" : "=r"(r) : "f"(f));
    return r;
}

__device__ __forceinline__ void mma_tf32(float4& c,
    uint32_t a0, uint32_t a1, uint32_t a2, uint32_t a3,
    uint32_t b0, uint32_t b1)
{
    asm volatile(
        "mma.sync.aligned.m16n8k8.row.col.f32.tf32.tf32.f32 "
        "{%0,%1,%2,%3}, {%4,%5,%6,%7}, {%8,%9}, {%0,%1,%2,%3};"
        : "+f"(c.x), "+f"(c.y), "+f"(c.z), "+f"(c.w)
        : "r"(a0), "r"(a1), "r"(a2), "r"(a3), "r"(b0), "r"(b1));
}

__device__ __forceinline__ void cp16(void* sm, const void* gm) {
    uint32_t sa = (uint32_t)__cvta_generic_to_shared(sm);
    asm volatile("cp.async.ca.shared.global [%0], [%1], 16;" :: "r"(sa), "l"(gm));
}
__device__ __forceinline__ void cp_commit() {
    asm volatile("cp.async.commit_group;" ::: "memory");
}
template <int Npend>
__device__ __forceinline__ void cp_wait() {
    asm volatile("cp.async.wait_group %0;" :: "n"(Npend) : "memory");
}

// ---------------- generic fills ----------------
__global__ void fill_f32(float* p, size_t n, float v) {
    size_t i = (size_t)blockIdx.x * blockDim.x + threadIdx.x;
    if (i < n) p[i] = v;
}

__global__ void init_md_k(float* m, float* den, int nh) {
    int i = blockIdx.x * blockDim.x + threadIdx.x;
    if (i < nh) { m[i] = -INFINITY; den[i] = 0.f; }
}

__global__ void init_bounds_k(int* start, int* end) {
    int i = threadIdx.x;
    if (i < NG) { start[i] = 1 << 30; end[i] = 0; }
}

// ================= tf32 tensor-core GEMM =================
// C[M,256] = A[M,K] @ B[K,256]; K multiple of 32.
// Block tile 128x128x32, 256 threads (8 warps), warp tile 64x32.
// Smem: A [128][36] m-major (pad 4), B [32][136] n-major (pad 8); 2 stages.
#define GBM 128
#define GBN 128
#define GBK 32
#define ASTR 36
#define BSTR 136
#define STAGE_F (GBM * ASTR + GBK * BSTR)   // floats per stage = 8960
#define GEMM_SMEM_BYTES (2 * STAGE_F * 4)   // 71680 bytes

__device__ __forceinline__ void gemm_load_tiles(
    float* As, float* Bs, const float* __restrict__ A, const float* __restrict__ B,
    int M, int K, int block_row, int block_col, int k0, int tid)
{
    // A tile: 128 rows x 32 floats = 1024 float4; 4 per thread
    int r0 = tid >> 3;             // 0..31
    int f4 = (tid & 7) * 4;        // 0..28
#pragma unroll
    for (int i = 0; i < 4; i++) {
        int r = r0 + i * 32;
        int gr = block_row + r;
        if (gr >= M) gr = M - 1;   // clamp: rows >= M never stored
        cp16(&As[r * ASTR + f4], &A[(size_t)gr * K + k0 + f4]);
    }
    // B tile: 32 rows x 128 floats = 1024 float4; 4 per thread
    int br0 = tid >> 5;            // 0..7
    int bf4 = (tid & 31) * 4;      // 0..124
#pragma unroll
    for (int i = 0; i < 4; i++) {
        int bk = br0 + i * 8;
        cp16(&Bs[bk * BSTR + bf4], &B[(size_t)(k0 + bk) * HCn + block_col + bf4]);
    }
    cp_commit();
}

__global__ __launch_bounds__(256) void gemm_tf32(
    const float* __restrict__ A, const float* __restrict__ B,
    float* __restrict__ C, int M, int K)
{
    extern __shared__ float smem[];
    const int tid  = threadIdx.x;
    const int lane = tid & 31;
    const int wid  = tid >> 5;
    const int warp_m = wid & 1;       // 0..1 -> 64-row halves
    const int warp_n = wid >> 1;      // 0..3 -> 32-col quarters
    const int gid = lane >> 2;        // 0..7
    const int tig = lane & 3;         // 0..3
    const int block_row = blockIdx.y * GBM;
    const int block_col = blockIdx.x * GBN;

    float4 acc[4][4];
#pragma unroll
    for (int i = 0; i < 4; i++)
#pragma unroll
        for (int j = 0; j < 4; j++) acc[i][j] = make_float4(0.f, 0.f, 0.f, 0.f);

    const int niter = K / GBK;

    // prologue: stage 0
    gemm_load_tiles(smem, smem + GBM * ASTR, A, B, M, K, block_row, block_col, 0, tid);

    for (int it = 0; it < niter; it++) {
        int cur = it & 1;
        if (it + 1 < niter) {
            float* As_n = smem + (1 - cur) * STAGE_F;
            gemm_load_tiles(As_n, As_n + GBM * ASTR, A, B, M, K, block_row, block_col,
                            (it + 1) * GBK, tid);
            cp_wait<1>();
        } else {
            cp_wait<0>();
        }
        __syncthreads();

        const float* As = smem + cur * STAGE_F;
        const float* Bs = As + GBM * ASTR;

#pragma unroll
        for (int ks = 0; ks < 4; ks++) {
            int kb = ks * 8;
            uint32_t af[4][4], bf[4][2];
#pragma unroll
            for (int tm = 0; tm < 4; tm++) {
                int row = warp_m * 64 + tm * 16 + gid;
                const float* ap = &As[row * ASTR + kb + tig];
                af[tm][0] = f2tf(ap[0]);
                af[tm][1] = f2tf(ap[8 * ASTR]);
                af[tm][2] = f2tf(ap[4]);
                af[tm][3] = f2tf(ap[8 * ASTR + 4]);
            }
#pragma unroll
            for (int tn = 0; tn < 4; tn++) {
                int col = warp_n * 32 + tn * 8 + gid;
                const float* bp = &Bs[(kb + tig) * BSTR + col];
                bf[tn][0] = f2tf(bp[0]);
                bf[tn][1] = f2tf(bp[4 * BSTR]);
            }
#pragma unroll
            for (int tm = 0; tm < 4; tm++)
#pragma unroll
                for (int tn = 0; tn < 4; tn++)
                    mma_tf32(acc[tm][tn], af[tm][0], af[tm][1], af[tm][2], af[tm][3],
                             bf[tn][0], bf[tn][1]);
        }
        __syncthreads();
    }

    // epilogue
#pragma unroll
    for (int tm = 0; tm < 4; tm++) {
        int grow0 = block_row + warp_m * 64 + tm * 16 + gid;
        int grow1 = grow0 + 8;
#pragma unroll
        for (int tn = 0; tn < 4; tn++) {
            int gcol = block_col + warp_n * 32 + tn * 8 + tig * 2;
            if (grow0 < M) {
                float2 v = make_float2(acc[tm][tn].x, acc[tm][tn].y);
                *(float2*)&C[(size_t)grow0 * HCn + gcol] = v;
            }
            if (grow1 < M) {
                float2 v = make_float2(acc[tm][tn].z, acc[tm][tn].w);
                *(float2*)&C[(size_t)grow1 * HCn + gcol] = v;
            }
        }
    }
}

// ---------------- attention scores ----------------
__global__ __launch_bounds__(256) void attn_scores(
    const float* __restrict__ h, const float* __restrict__ att_src,
    const float* __restrict__ att_dst, float* __restrict__ a_src,
    float* __restrict__ a_dst, int N)
{
    __shared__ float s_src[HCn], s_dst[HCn];
    int tid = threadIdx.x;
    s_src[tid] = att_src[tid];
    s_dst[tid] = att_dst[tid];
    __syncthreads();
    int warp = (int)((blockIdx.x * (size_t)blockDim.x + tid) >> 5);
    int lane = tid & 31;
    if (warp >= N) return;
    float ss = 0.f, sd = 0.f;
    const float4* hp = (const float4*)&h[(size_t)warp * HCn + lane * 8];
    const float4* sp = (const float4*)&s_src[lane * 8];
    const float4* dp = (const float4*)&s_dst[lane * 8];
#pragma unroll
    for (int j = 0; j < 2; j++) {
        float4 hv = hp[j], as = sp[j], ad = dp[j];
        ss += hv.x * as.x + hv.y * as.y + hv.z * as.z + hv.w * as.w;
        sd += hv.x * ad.x + hv.y * ad.y + hv.z * ad.z + hv.w * ad.w;
    }
#pragma unroll
    for (int o = 4; o; o >>= 1) {
        ss += __shfl_xor_sync(0xffffffffu, ss, o);
        sd += __shfl_xor_sync(0xffffffffu, sd, o);
    }
    if ((lane & 7) == 0) {
        int head = lane >> 3;
        a_src[warp * Hh + head] = ss;
        a_dst[warp * Hh + head] = sd;
    }
}

// ---------------- edge pass 1: per-dst max ----------------
__global__ __launch_bounds__(256) void edge_max_k(
    const int* __restrict__ ei, int E, int N,
    const float* __restrict__ a_src, const float* __restrict__ a_dst,
    float* __restrict__ m)
{
    int i = blockIdx.x * blockDim.x + threadIdx.x;
    int ET = E + N;
    if (i >= ET) return;
    int s, d;
    if (i < E) { s = ei[i]; d = ei[E + i]; }
    else       { s = d = i - E; }
    if ((unsigned)s >= (unsigned)N || (unsigned)d >= (unsigned)N) return;
    float4 as = *(const float4*)&a_src[s * Hh];
    float4 ad = *(const float4*)&a_dst[d * Hh];
    atomicMaxF(&m[d * Hh + 0], lrelu(as.x + ad.x));
    atomicMaxF(&m[d * Hh + 1], lrelu(as.y + ad.y));
    atomicMaxF(&m[d * Hh + 2], lrelu(as.z + ad.z));
    atomicMaxF(&m[d * Hh + 3], lrelu(as.w + ad.w));
}

// ---------------- edge pass 2: denom ----------------
__global__ __launch_bounds__(256) void edge_den_k(
    const int* __restrict__ ei, int E, int N,
    const float* __restrict__ a_src, const float* __restrict__ a_dst,
    const float* __restrict__ m, float* __restrict__ den)
{
    int i = blockIdx.x * blockDim.x + threadIdx.x;
    int ET = E + N;
    if (i >= ET) return;
    int s, d;
    if (i < E) { s = ei[i]; d = ei[E + i]; }
    else       { s = d = i - E; }
    if ((unsigned)s >= (unsigned)N || (unsigned)d >= (unsigned)N) return;
    float4 as = *(const float4*)&a_src[s * Hh];
    float4 ad = *(const float4*)&a_dst[d * Hh];
    float4 mm = *(const float4*)&m[d * Hh];
    atomicAdd(&den[d * Hh + 0], expf(lrelu(as.x + ad.x) - mm.x));
    atomicAdd(&den[d * Hh + 1], expf(lrelu(as.y + ad.y) - mm.y));
    atomicAdd(&den[d * Hh + 2], expf(lrelu(as.z + ad.z) - mm.z));
    atomicAdd(&den[d * Hh + 3], expf(lrelu(as.w + ad.w) - mm.w));
}

// ---------------- edge pass 3: agg[dst] += p * h[src] ----------------
__global__ __launch_bounds__(256) void edge_agg_k(
    const int* __restrict__ ei, int E, int N,
    const float* __restrict__ a_src, const float* __restrict__ a_dst,
    const float* __restrict__ m,
    const float* __restrict__ h, float* __restrict__ agg)
{
    int gw = (int)(((size_t)blockIdx.x * blockDim.x + threadIdx.x) >> 5);
    int lane = threadIdx.x & 31;
    int ET = E + N;
    if (gw >= ET) return;
    int s = 0, d = 0;
    if (lane == 0) {
        if (gw < E) { s = ei[gw]; d = ei[E + gw]; }
        else        { s = d = gw - E; }
    }
    s = __shfl_sync(0xffffffffu, s, 0);
    d = __shfl_sync(0xffffffffu, d, 0);
    if ((unsigned)s >= (unsigned)N || (unsigned)d >= (unsigned)N) return;
    int head = lane >> 3;
    float e = lrelu(a_src[s * Hh + head] + a_dst[d * Hh + head]);
    float p = expf(e - m[d * Hh + head]);
    const float4* hp = (const float4*)&h[(size_t)s * HCn + lane * 8];
    float4 v0 = hp[0], v1 = hp[1];
    v0.x *= p; v0.y *= p; v0.z *= p; v0.w *= p;
    v1.x *= p; v1.y *= p; v1.z *= p; v1.w *= p;
    float* dst0 = &agg[(size_t)d * HCn + lane * 8];
    red_add_v4(dst0, v0);
    red_add_v4(dst0 + 4, v1);
}

// ---------------- layer-1 epilogue ----------------
__global__ __launch_bounds__(256) void finalize1_k(
    const float* __restrict__ agg, const float* __restrict__ den,
    const float* __restrict__ b1, float* __restrict__ h2, int N)
{
    size_t i = (size_t)blockIdx.x * blockDim.x + threadIdx.x;
    if (i >= (size_t)N * HCn) return;
    int c256 = (int)(i & (HCn - 1));
    int n = (int)(i >> 8);
    int head = c256 >> 6;
    float v = agg[i] / den[n * Hh + head] + b1[c256];
    h2[i] = elu1(v);
}

// ---------------- layer-2 epilogue ----------------
__global__ __launch_bounds__(256) void finalize2_k(
    const float* __restrict__ agg, const float* __restrict__ den,
    const float* __restrict__ b2, float* __restrict__ hf, int N)
{
    size_t i = (size_t)blockIdx.x * blockDim.x + threadIdx.x;
    if (i >= (size_t)N * Cc) return;
    int c = (int)(i & (Cc - 1));
    int n = (int)(i >> 6);
    const float* ar = &agg[(size_t)n * HCn];
    const float* dr = &den[n * Hh];
    float v = 0.f;
#pragma unroll
    for (int hd = 0; hd < Hh; hd++) v += ar[hd * Cc + c] / dr[hd];
    v = v * 0.25f + b2[c];
    hf[i] = elu1(v);
}

// ---------------- pooling ----------------
__global__ void graph_bounds_k(const int* __restrict__ batch, int N,
                               int* __restrict__ start, int* __restrict__ end)
{
    int n = blockIdx.x * blockDim.x + threadIdx.x;
    if (n >= N) return;
    int g = batch[n];
    if (g < 0 || g >= NG) return;
    atomicMin(&start[g], n);
    atomicMax(&end[g], n + 1);
}

__global__ __launch_bounds__(256) void pool_k(
    const float* __restrict__ hf, const int* __restrict__ start,
    const int* __restrict__ end, float* __restrict__ pooled)
{
    int g = blockIdx.x;
    int tid = threadIdx.x;
    int col = tid & 63, sub = tid >> 6;
    int s = start[g], e = end[g];
    if (s > e) { s = 0; e = 0; }
    float acc = 0.f;
    for (int n = s + sub; n < e; n += 4) acc += hf[(size_t)n * Cc + col];
    __shared__ float sm[256];
    sm[tid] = acc;
    __syncthreads();
    if (sub == 0) {
        float v = sm[col] + sm[64 + col] + sm[128 + col] + sm[192 + col];
        float cnt = (e > s) ? (float)(e - s) : 0.f;
        pooled[g * Cc + col] = v / fmaxf(cnt, 1.0f);
    }
}

// ---------------- final head ----------------
__global__ __launch_bounds__(1024) void head_k(
    const float* __restrict__ pooled, const float* __restrict__ Wa,
    const float* __restrict__ ba, float* __restrict__ out)
{
    __shared__ float sW[Cc * NA];
    int t = threadIdx.y * 32 + threadIdx.x;
    for (int i = t; i < Cc * NA; i += 1024) sW[i] = Wa[i];
    __syncthreads();
    int a = threadIdx.x;
#pragma unroll
    for (int rep = 0; rep < 2; rep++) {
        int g = threadIdx.y + rep * 32;
        float acc = ba[a];
#pragma unroll 8
        for (int c = 0; c < Cc; c++) acc = fmaf(pooled[g * Cc + c], sW[c * NA + a], acc);
        out[g * NA + a] = acc;
    }
}

// ---------------- host orchestration ----------------
static float* symf(const void* sym) {
    void* p = nullptr;
    cudaGetSymbolAddress(&p, sym);
    return (float*)p;
}
static int* symi(const void* sym) {
    void* p = nullptr;
    cudaGetSymbolAddress(&p, sym);
    return (int*)p;
}

static void run_gat_layer(const float* in, int M, int K,
                          const float* W, const float* att_s, const float* att_d,
                          const int* ei, int E, int N,
                          float* h, float* agg, float* asrc, float* adst,
                          float* m, float* den)
{
    dim3 gg(HCn / GBN, (M + GBM - 1) / GBM);
    gemm_tf32<<<gg, 256, GEMM_SMEM_BYTES>>>(in, W, h, M, K);
    {
        size_t threads = (size_t)N * 32;
        attn_scores<<<(unsigned)((threads + 255) / 256), 256>>>(h, att_s, att_d, asrc, adst, N);
    }
    init_md_k<<<(N * Hh + 255) / 256, 256>>>(m, den, N * Hh);
    fill_f32<<<(unsigned)(((size_t)N * HCn + 255) / 256), 256>>>(agg, (size_t)N * HCn, 0.f);
    int ET = E + N;
    edge_max_k<<<(ET + 255) / 256, 256>>>(ei, E, N, asrc, adst, m);
    edge_den_k<<<(ET + 255) / 256, 256>>>(ei, E, N, asrc, adst, m, den);
    {
        size_t threads = (size_t)ET * 32;
        edge_agg_k<<<(unsigned)((threads + 255) / 256), 256>>>(ei, E, N, asrc, adst, m, h, agg);
    }
}

extern "C" void kernel_launch(void* const* d_in, const int* in_sizes, int n_in,
                              void* d_out, int out_size)
{
    // allow >48KB dynamic smem for the GEMM (idempotent, cheap)
    static int smem_set = 0;
    if (!smem_set) {
        cudaFuncSetAttribute(gemm_tf32, cudaFuncAttributeMaxDynamicSharedMemorySize,
                             GEMM_SMEM_BYTES);
        smem_set = 1;
    }

    // -------- robust input mapping (filter size-1 scalar inputs) --------
    const void* t[13];
    int tsz[13];
    int cnt = 0;
    for (int i = 0; i < n_in && cnt < 13; i++) {
        if (in_sizes[i] <= 1) continue;
        t[cnt] = d_in[i];
        tsz[cnt] = in_sizes[i];
        cnt++;
    }
    if (cnt < 13) return;

    const float* x     = (const float*)t[0];
    const int*   ei    = (const int*)t[1];
    const int*   batch = (const int*)t[2];
    const float* W1    = (const float*)t[3];
    const float* attS1 = (const float*)t[4];
    const float* attD1 = (const float*)t[5];
    const float* b1    = (const float*)t[6];
    const float* W2    = (const float*)t[7];
    const float* attS2 = (const float*)t[8];
    const float* attD2 = (const float*)t[9];
    const float* b2    = (const float*)t[10];
    const float* Wa    = (const float*)t[11];
    const float* ba    = (const float*)t[12];

    const int Fin = 128;
    int N = tsz[0] / Fin;
    int E = tsz[1] / 2;
    if (N > MAXN || E > MAXE || N <= 0 || E <= 0) return;

    float* h    = symf(g_h);
    float* agg  = symf(g_agg);
    float* h2   = symf(g_h2);
    float* asrc = symf(g_asrc);
    float* adst = symf(g_adst);
    float* m    = symf(g_m);
    float* den  = symf(g_den);
    float* hf   = symf(g_hf);
    float* pooled = symf(g_pooled);
    int* gstart = symi(g_start);
    int* gend   = symi(g_end);

    // ---- layer 1 ----
    run_gat_layer(x, N, Fin, W1, attS1, attD1, ei, E, N, h, agg, asrc, adst, m, den);
    finalize1_k<<<(unsigned)(((size_t)N * HCn + 255) / 256), 256>>>(agg, den, b1, h2, N);

    // ---- layer 2 ----
    run_gat_layer(h2, N, HCn, W2, attS2, attD2, ei, E, N, h, agg, asrc, adst, m, den);
    finalize2_k<<<(unsigned)(((size_t)N * Cc + 255) / 256), 256>>>(agg, den, b2, hf, N);

    // ---- pooling ----
    init_bounds_k<<<1, 64>>>(gstart, gend);
    fill_f32<<<(NG * Cc + 255) / 256, 256>>>(pooled, NG * Cc, 0.f);
    graph_bounds_k<<<(N + 255) / 256, 256>>>(batch, N, gstart, gend);
    pool_k<<<NG, 256>>>(hf, gstart, gend, pooled);

    // ---- head ----
    head_k<<<1, dim3(32, 32)>>>(pooled, Wa, ba, (float*)d_out);
}

// round 5
// speedup vs baseline: 1.4071x; 1.2060x over previous
#include <cuda_runtime.h>
#include <math.h>
#include <stdio.h>
#include <stdint.h>

// ---------------- static problem capacities ----------------
#define MAXN 50000
#define MAXE 800000
#define HCn  256      // H*C
#define Hh   4
#define Cc   64
#define NG   64       // graphs
#define NA   32       // actions

// ---------------- device scratch (allocation-free rule) ----------------
__device__ float g_h  [(size_t)MAXN * HCn];   // projection buffer (reused both layers)
__device__ float g_agg[(size_t)MAXN * HCn];   // aggregation buffer (reused both layers)
__device__ float g_h2 [(size_t)MAXN * HCn];   // layer-2 input
__device__ float g_asrc[MAXN * Hh];
__device__ float g_adst[MAXN * Hh];
__device__ float g_den [MAXN * Hh];
__device__ float g_hf  [(size_t)MAXN * Cc];   // final node features [N,64]
__device__ float g_pooled[NG * Cc];
__device__ int   g_start[NG];
__device__ int   g_end  [NG];

// ---------------- helpers ----------------
__device__ __forceinline__ float lrelu(float x) { return fmaxf(x, 0.2f * x); }
__device__ __forceinline__ float elu1(float x)  { return x > 0.f ? x : expm1f(x); }

__device__ __forceinline__ void red_add_v4(float* a, float4 v) {
    asm volatile("red.global.add.v4.f32 [%0], {%1,%2,%3,%4};"
                 :: "l"(a), "f"(v.x), "f"(v.y), "f"(v.z), "f"(v.w) : "memory");
}

__device__ __forceinline__ uint32_t f2tf(float f) {
    uint32_t r;
    asm("cvt.rna.tf32.f32 %0, %1;" : "=r"(r) : "f"(f));
    return r;
}

__device__ __forceinline__ void mma_tf32(float4& c,
    uint32_t a0, uint32_t a1, uint32_t a2, uint32_t a3,
    uint32_t b0, uint32_t b1)
{
    asm volatile(
        "mma.sync.aligned.m16n8k8.row.col.f32.tf32.tf32.f32 "
        "{%0,%1,%2,%3}, {%4,%5,%6,%7}, {%8,%9}, {%0,%1,%2,%3};"
        : "+f"(c.x), "+f"(c.y), "+f"(c.z), "+f"(c.w)
        : "r"(a0), "r"(a1), "r"(a2), "r"(a3), "r"(b0), "r"(b1));
}

__device__ __forceinline__ void cp16(void* sm, const void* gm) {
    uint32_t sa = (uint32_t)__cvta_generic_to_shared(sm);
    asm volatile("cp.async.ca.shared.global [%0], [%1], 16;" :: "r"(sa), "l"(gm));
}
__device__ __forceinline__ void cp_commit() {
    asm volatile("cp.async.commit_group;" ::: "memory");
}
template <int Npend>
__device__ __forceinline__ void cp_wait() {
    asm volatile("cp.async.wait_group %0;" :: "n"(Npend) : "memory");
}

// ---------------- generic fill ----------------
__global__ void fill_f32(float* p, size_t n, float v) {
    size_t i = (size_t)blockIdx.x * blockDim.x + threadIdx.x;
    if (i < n) p[i] = v;
}

__global__ void init_bounds_k(int* start, int* end) {
    int i = threadIdx.x;
    if (i < NG) { start[i] = 1 << 30; end[i] = 0; }
}

// ================= tf32 tensor-core GEMM =================
// C[M,256] = A[M,K] @ B[K,256]; K multiple of 32.
// Block tile 128x128x32, 256 threads (8 warps), warp tile 64x32.
#define GBM 128
#define GBN 128
#define GBK 32
#define ASTR 36
#define BSTR 136
#define STAGE_F (GBM * ASTR + GBK * BSTR)   // floats per stage = 8960
#define GEMM_SMEM_BYTES (2 * STAGE_F * 4)   // 71680 bytes

__device__ __forceinline__ void gemm_load_tiles(
    float* As, float* Bs, const float* __restrict__ A, const float* __restrict__ B,
    int M, int K, int block_row, int block_col, int k0, int tid)
{
    int r0 = tid >> 3;             // 0..31
    int f4 = (tid & 7) * 4;        // 0..28
#pragma unroll
    for (int i = 0; i < 4; i++) {
        int r = r0 + i * 32;
        int gr = block_row + r;
        if (gr >= M) gr = M - 1;   // clamp: rows >= M never stored
        cp16(&As[r * ASTR + f4], &A[(size_t)gr * K + k0 + f4]);
    }
    int br0 = tid >> 5;            // 0..7
    int bf4 = (tid & 31) * 4;      // 0..124
#pragma unroll
    for (int i = 0; i < 4; i++) {
        int bk = br0 + i * 8;
        cp16(&Bs[bk * BSTR + bf4], &B[(size_t)(k0 + bk) * HCn + block_col + bf4]);
    }
    cp_commit();
}

__global__ __launch_bounds__(256) void gemm_tf32(
    const float* __restrict__ A, const float* __restrict__ B,
    float* __restrict__ C, int M, int K)
{
    extern __shared__ float smem[];
    const int tid  = threadIdx.x;
    const int lane = tid & 31;
    const int wid  = tid >> 5;
    const int warp_m = wid & 1;
    const int warp_n = wid >> 1;
    const int gid = lane >> 2;
    const int tig = lane & 3;
    const int block_row = blockIdx.y * GBM;
    const int block_col = blockIdx.x * GBN;

    float4 acc[4][4];
#pragma unroll
    for (int i = 0; i < 4; i++)
#pragma unroll
        for (int j = 0; j < 4; j++) acc[i][j] = make_float4(0.f, 0.f, 0.f, 0.f);

    const int niter = K / GBK;
    gemm_load_tiles(smem, smem + GBM * ASTR, A, B, M, K, block_row, block_col, 0, tid);

    for (int it = 0; it < niter; it++) {
        int cur = it & 1;
        if (it + 1 < niter) {
            float* As_n = smem + (1 - cur) * STAGE_F;
            gemm_load_tiles(As_n, As_n + GBM * ASTR, A, B, M, K, block_row, block_col,
                            (it + 1) * GBK, tid);
            cp_wait<1>();
        } else {
            cp_wait<0>();
        }
        __syncthreads();

        const float* As = smem + cur * STAGE_F;
        const float* Bs = As + GBM * ASTR;

#pragma unroll
        for (int ks = 0; ks < 4; ks++) {
            int kb = ks * 8;
            uint32_t af[4][4], bf[4][2];
#pragma unroll
            for (int tm = 0; tm < 4; tm++) {
                int row = warp_m * 64 + tm * 16 + gid;
                const float* ap = &As[row * ASTR + kb + tig];
                af[tm][0] = f2tf(ap[0]);
                af[tm][1] = f2tf(ap[8 * ASTR]);
                af[tm][2] = f2tf(ap[4]);
                af[tm][3] = f2tf(ap[8 * ASTR + 4]);
            }
#pragma unroll
            for (int tn = 0; tn < 4; tn++) {
                int col = warp_n * 32 + tn * 8 + gid;
                const float* bp = &Bs[(kb + tig) * BSTR + col];
                bf[tn][0] = f2tf(bp[0]);
                bf[tn][1] = f2tf(bp[4 * BSTR]);
            }
#pragma unroll
            for (int tm = 0; tm < 4; tm++)
#pragma unroll
                for (int tn = 0; tn < 4; tn++)
                    mma_tf32(acc[tm][tn], af[tm][0], af[tm][1], af[tm][2], af[tm][3],
                             bf[tn][0], bf[tn][1]);
        }
        __syncthreads();
    }

#pragma unroll
    for (int tm = 0; tm < 4; tm++) {
        int grow0 = block_row + warp_m * 64 + tm * 16 + gid;
        int grow1 = grow0 + 8;
#pragma unroll
        for (int tn = 0; tn < 4; tn++) {
            int gcol = block_col + warp_n * 32 + tn * 8 + tig * 2;
            if (grow0 < M) {
                float2 v = make_float2(acc[tm][tn].x, acc[tm][tn].y);
                *(float2*)&C[(size_t)grow0 * HCn + gcol] = v;
            }
            if (grow1 < M) {
                float2 v = make_float2(acc[tm][tn].z, acc[tm][tn].w);
                *(float2*)&C[(size_t)grow1 * HCn + gcol] = v;
            }
        }
    }
}

// ---------------- attention scores + zero agg/den ----------------
// one warp per node; also zeroes agg[n,:] and den[n,:] for the coming edge pass
__global__ __launch_bounds__(256) void attn_scores(
    const float* __restrict__ h, const float* __restrict__ att_src,
    const float* __restrict__ att_dst, float* __restrict__ a_src,
    float* __restrict__ a_dst, float* __restrict__ agg,
    float* __restrict__ den, int N)
{
    __shared__ float s_src[HCn], s_dst[HCn];
    int tid = threadIdx.x;
    s_src[tid] = att_src[tid];
    s_dst[tid] = att_dst[tid];
    __syncthreads();
    int warp = (int)((blockIdx.x * (size_t)blockDim.x + tid) >> 5);
    int lane = tid & 31;
    if (warp >= N) return;

    // zero agg row (256 floats = 32 lanes x 2 float4)
    float4 z = make_float4(0.f, 0.f, 0.f, 0.f);
    float4* ap4 = (float4*)&agg[(size_t)warp * HCn + lane * 8];
    ap4[0] = z;
    ap4[1] = z;
    if (lane < Hh) den[warp * Hh + lane] = 0.f;

    float ss = 0.f, sd = 0.f;
    const float4* hp = (const float4*)&h[(size_t)warp * HCn + lane * 8];
    const float4* sp = (const float4*)&s_src[lane * 8];
    const float4* dp = (const float4*)&s_dst[lane * 8];
#pragma unroll
    for (int j = 0; j < 2; j++) {
        float4 hv = hp[j], as = sp[j], ad = dp[j];
        ss += hv.x * as.x + hv.y * as.y + hv.z * as.z + hv.w * as.w;
        sd += hv.x * ad.x + hv.y * ad.y + hv.z * ad.z + hv.w * ad.w;
    }
#pragma unroll
    for (int o = 4; o; o >>= 1) {
        ss += __shfl_xor_sync(0xffffffffu, ss, o);
        sd += __shfl_xor_sync(0xffffffffu, sd, o);
    }
    if ((lane & 7) == 0) {
        int head = lane >> 3;
        a_src[warp * Hh + head] = ss;
        a_dst[warp * Hh + head] = sd;
    }
}

// ---------------- fused edge pass: den[dst] += p; agg[dst] += p*h[src] ----------------
// softmax is shift-invariant; scores are small, so no max subtraction needed.
__global__ __launch_bounds__(256) void edge_fused_k(
    const int* __restrict__ ei, int E, int N,
    const float* __restrict__ a_src, const float* __restrict__ a_dst,
    const float* __restrict__ h, float* __restrict__ agg,
    float* __restrict__ den)
{
    int gw = (int)(((size_t)blockIdx.x * blockDim.x + threadIdx.x) >> 5);
    int lane = threadIdx.x & 31;
    int ET = E + N;
    if (gw >= ET) return;
    int s = 0, d = 0;
    if (lane == 0) {
        if (gw < E) { s = ei[gw]; d = ei[E + gw]; }
        else        { s = d = gw - E; }
    }
    s = __shfl_sync(0xffffffffu, s, 0);
    d = __shfl_sync(0xffffffffu, d, 0);
    if ((unsigned)s >= (unsigned)N || (unsigned)d >= (unsigned)N) return;
    int head = lane >> 3;
    float e = lrelu(a_src[s * Hh + head] + a_dst[d * Hh + head]);
    float p = expf(e);
    if ((lane & 7) == 0) atomicAdd(&den[d * Hh + head], p);
    const float4* hp = (const float4*)&h[(size_t)s * HCn + lane * 8];
    float4 v0 = hp[0], v1 = hp[1];
    v0.x *= p; v0.y *= p; v0.z *= p; v0.w *= p;
    v1.x *= p; v1.y *= p; v1.z *= p; v1.w *= p;
    float* dst0 = &agg[(size_t)d * HCn + lane * 8];
    red_add_v4(dst0, v0);
    red_add_v4(dst0 + 4, v1);
}

// ---------------- layer-1 epilogue ----------------
__global__ __launch_bounds__(256) void finalize1_k(
    const float* __restrict__ agg, const float* __restrict__ den,
    const float* __restrict__ b1, float* __restrict__ h2, int N)
{
    size_t i = (size_t)blockIdx.x * blockDim.x + threadIdx.x;
    if (i >= (size_t)N * HCn) return;
    int c256 = (int)(i & (HCn - 1));
    int n = (int)(i >> 8);
    int head = c256 >> 6;
    float v = agg[i] / den[n * Hh + head] + b1[c256];
    h2[i] = elu1(v);
}

// ---------------- layer-2 epilogue ----------------
__global__ __launch_bounds__(256) void finalize2_k(
    const float* __restrict__ agg, const float* __restrict__ den,
    const float* __restrict__ b2, float* __restrict__ hf, int N)
{
    size_t i = (size_t)blockIdx.x * blockDim.x + threadIdx.x;
    if (i >= (size_t)N * Cc) return;
    int c = (int)(i & (Cc - 1));
    int n = (int)(i >> 6);
    const float* ar = &agg[(size_t)n * HCn];
    const float* dr = &den[n * Hh];
    float v = 0.f;
#pragma unroll
    for (int hd = 0; hd < Hh; hd++) v += ar[hd * Cc + c] / dr[hd];
    v = v * 0.25f + b2[c];
    hf[i] = elu1(v);
}

// ---------------- pooling ----------------
__global__ void graph_bounds_k(const int* __restrict__ batch, int N,
                               int* __restrict__ start, int* __restrict__ end)
{
    int n = blockIdx.x * blockDim.x + threadIdx.x;
    if (n >= N) return;
    int g = batch[n];
    if (g < 0 || g >= NG) return;
    atomicMin(&start[g], n);
    atomicMax(&end[g], n + 1);
}

__global__ __launch_bounds__(256) void pool_k(
    const float* __restrict__ hf, const int* __restrict__ start,
    const int* __restrict__ end, float* __restrict__ pooled)
{
    int g = blockIdx.x;
    int tid = threadIdx.x;
    int col = tid & 63, sub = tid >> 6;
    int s = start[g], e = end[g];
    if (s > e) { s = 0; e = 0; }
    float acc = 0.f;
    for (int n = s + sub; n < e; n += 4) acc += hf[(size_t)n * Cc + col];
    __shared__ float sm[256];
    sm[tid] = acc;
    __syncthreads();
    if (sub == 0) {
        float v = sm[col] + sm[64 + col] + sm[128 + col] + sm[192 + col];
        float cnt = (e > s) ? (float)(e - s) : 0.f;
        pooled[g * Cc + col] = v / fmaxf(cnt, 1.0f);
    }
}

// ---------------- final head ----------------
__global__ __launch_bounds__(1024) void head_k(
    const float* __restrict__ pooled, const float* __restrict__ Wa,
    const float* __restrict__ ba, float* __restrict__ out)
{
    __shared__ float sW[Cc * NA];
    int t = threadIdx.y * 32 + threadIdx.x;
    for (int i = t; i < Cc * NA; i += 1024) sW[i] = Wa[i];
    __syncthreads();
    int a = threadIdx.x;
#pragma unroll
    for (int rep = 0; rep < 2; rep++) {
        int g = threadIdx.y + rep * 32;
        float acc = ba[a];
#pragma unroll 8
        for (int c = 0; c < Cc; c++) acc = fmaf(pooled[g * Cc + c], sW[c * NA + a], acc);
        out[g * NA + a] = acc;
    }
}

// ---------------- host orchestration ----------------
static float* symf(const void* sym) {
    void* p = nullptr;
    cudaGetSymbolAddress(&p, sym);
    return (float*)p;
}
static int* symi(const void* sym) {
    void* p = nullptr;
    cudaGetSymbolAddress(&p, sym);
    return (int*)p;
}

static void run_gat_layer(const float* in, int M, int K,
                          const float* W, const float* att_s, const float* att_d,
                          const int* ei, int E, int N,
                          float* h, float* agg, float* asrc, float* adst, float* den)
{
    dim3 gg(HCn / GBN, (M + GBM - 1) / GBM);
    gemm_tf32<<<gg, 256, GEMM_SMEM_BYTES>>>(in, W, h, M, K);
    {
        size_t threads = (size_t)N * 32;
        attn_scores<<<(unsigned)((threads + 255) / 256), 256>>>(
            h, att_s, att_d, asrc, adst, agg, den, N);
    }
    int ET = E + N;
    {
        size_t threads = (size_t)ET * 32;
        edge_fused_k<<<(unsigned)((threads + 255) / 256), 256>>>(
            ei, E, N, asrc, adst, h, agg, den);
    }
}

extern "C" void kernel_launch(void* const* d_in, const int* in_sizes, int n_in,
                              void* d_out, int out_size)
{
    static int smem_set = 0;
    if (!smem_set) {
        cudaFuncSetAttribute(gemm_tf32, cudaFuncAttributeMaxDynamicSharedMemorySize,
                             GEMM_SMEM_BYTES);
        smem_set = 1;
    }

    // -------- robust input mapping (filter size-1 scalar inputs) --------
    const void* t[13];
    int tsz[13];
    int cnt = 0;
    for (int i = 0; i < n_in && cnt < 13; i++) {
        if (in_sizes[i] <= 1) continue;
        t[cnt] = d_in[i];
        tsz[cnt] = in_sizes[i];
        cnt++;
    }
    if (cnt < 13) return;

    const float* x     = (const float*)t[0];
    const int*   ei    = (const int*)t[1];
    const int*   batch = (const int*)t[2];
    const float* W1    = (const float*)t[3];
    const float* attS1 = (const float*)t[4];
    const float* attD1 = (const float*)t[5];
    const float* b1    = (const float*)t[6];
    const float* W2    = (const float*)t[7];
    const float* attS2 = (const float*)t[8];
    const float* attD2 = (const float*)t[9];
    const float* b2    = (const float*)t[10];
    const float* Wa    = (const float*)t[11];
    const float* ba    = (const float*)t[12];

    const int Fin = 128;
    int N = tsz[0] / Fin;
    int E = tsz[1] / 2;
    if (N > MAXN || E > MAXE || N <= 0 || E <= 0) return;

    float* h    = symf(g_h);
    float* agg  = symf(g_agg);
    float* h2   = symf(g_h2);
    float* asrc = symf(g_asrc);
    float* adst = symf(g_adst);
    float* den  = symf(g_den);
    float* hf   = symf(g_hf);
    float* pooled = symf(g_pooled);
    int* gstart = symi(g_start);
    int* gend   = symi(g_end);

    // ---- layer 1 ----
    run_gat_layer(x, N, Fin, W1, attS1, attD1, ei, E, N, h, agg, asrc, adst, den);
    finalize1_k<<<(unsigned)(((size_t)N * HCn + 255) / 256), 256>>>(agg, den, b1, h2, N);

    // ---- layer 2 ----
    run_gat_layer(h2, N, HCn, W2, attS2, attD2, ei, E, N, h, agg, asrc, adst, den);
    finalize2_k<<<(unsigned)(((size_t)N * Cc + 255) / 256), 256>>>(agg, den, b2, hf, N);

    // ---- pooling ----
    init_bounds_k<<<1, 64>>>(gstart, gend);
    fill_f32<<<(NG * Cc + 255) / 256, 256>>>(pooled, NG * Cc, 0.f);
    graph_bounds_k<<<(N + 255) / 256, 256>>>(batch, N, gstart, gend);
    pool_k<<<NG, 256>>>(hf, gstart, gend, pooled);

    // ---- head ----
    head_k<<<1, dim3(32, 32)>>>(pooled, Wa, ba, (float*)d_out);
}

// round 6
// speedup vs baseline: 2.4798x; 1.7624x over previous
#include <cuda_runtime.h>
#include <math.h>
#include <stdio.h>
#include <stdint.h>

// ---------------- static problem capacities ----------------
#define MAXN 50000
#define MAXE 800000
#define HCn  256      // H*C
#define Hh   4
#define Cc   64
#define NG   64       // graphs
#define NA   32       // actions

// ---------------- device scratch (allocation-free rule) ----------------
__device__ float g_h  [(size_t)MAXN * HCn];   // gemm output (both layers)
__device__ float g_h2 [(size_t)MAXN * HCn];   // layer-1 output / layer-2 input
__device__ float g_asrc[MAXN * Hh];
__device__ float g_adst[MAXN * Hh];
__device__ float g_hf  [(size_t)MAXN * Cc];   // final node features [N,64]
__device__ float g_pooled[NG * Cc];
__device__ int   g_start[NG];
__device__ int   g_end  [NG];
__device__ int   g_rowptr[MAXN + 1];
__device__ int   g_cursor[MAXN];
__device__ int   g_csr[MAXE];

// ---------------- helpers ----------------
__device__ __forceinline__ float lrelu(float x) { return fmaxf(x, 0.2f * x); }
__device__ __forceinline__ float elu1(float x)  { return x > 0.f ? x : expm1f(x); }

__device__ __forceinline__ uint32_t f2tf(float f) {
    uint32_t r;
    asm("cvt.rna.tf32.f32 %0, %1;" : "=r"(r) : "f"(f));
    return r;
}

__device__ __forceinline__ void mma_tf32(float4& c,
    uint32_t a0, uint32_t a1, uint32_t a2, uint32_t a3,
    uint32_t b0, uint32_t b1)
{
    asm volatile(
        "mma.sync.aligned.m16n8k8.row.col.f32.tf32.tf32.f32 "
        "{%0,%1,%2,%3}, {%4,%5,%6,%7}, {%8,%9}, {%0,%1,%2,%3};"
        : "+f"(c.x), "+f"(c.y), "+f"(c.z), "+f"(c.w)
        : "r"(a0), "r"(a1), "r"(a2), "r"(a3), "r"(b0), "r"(b1));
}

__device__ __forceinline__ void cp16(void* sm, const void* gm) {
    uint32_t sa = (uint32_t)__cvta_generic_to_shared(sm);
    asm volatile("cp.async.ca.shared.global [%0], [%1], 16;" :: "r"(sa), "l"(gm));
}
__device__ __forceinline__ void cp_commit() {
    asm volatile("cp.async.commit_group;" ::: "memory");
}
template <int Npend>
__device__ __forceinline__ void cp_wait() {
    asm volatile("cp.async.wait_group %0;" :: "n"(Npend) : "memory");
}

// ---------------- small utility kernels ----------------
__global__ void fill_f32(float* p, size_t n, float v) {
    size_t i = (size_t)blockIdx.x * blockDim.x + threadIdx.x;
    if (i < n) p[i] = v;
}

__global__ void zero_attn_k(float* a, float* b, int n) {
    int i = blockIdx.x * blockDim.x + threadIdx.x;
    if (i < n) { a[i] = 0.f; b[i] = 0.f; }
}

__global__ void init_bounds_k(int* start, int* end) {
    int i = threadIdx.x;
    if (i < NG) { start[i] = 1 << 30; end[i] = 0; }
}

// ---------------- CSR build (by destination) ----------------
__global__ void zero_deg_k(int* deg, int n) {
    int i = blockIdx.x * blockDim.x + threadIdx.x;
    if (i < n) deg[i] = 0;
}

__global__ void count_k(const int* __restrict__ ei, int E, int N, int* __restrict__ deg) {
    int i = blockIdx.x * blockDim.x + threadIdx.x;
    if (i >= E) return;
    int d = ei[E + i];
    if ((unsigned)d < (unsigned)N) atomicAdd(&deg[d], 1);
}

// single block of 1024 threads: exclusive scan of deg[0..N) -> row_ptr, cursor
__global__ __launch_bounds__(1024) void scan_k(
    const int* __restrict__ deg, int* __restrict__ row_ptr,
    int* __restrict__ cursor, int N)
{
    __shared__ int part[1024];
    int t = threadIdx.x;
    int chunk = (N + 1023) / 1024;
    int b = t * chunk, e = min(b + chunk, N);
    int sum = 0;
    for (int i = b; i < e; i++) sum += deg[i];
    part[t] = sum;
    __syncthreads();
    // Kogge-Stone inclusive scan
    for (int off = 1; off < 1024; off <<= 1) {
        int v = (t >= off) ? part[t - off] : 0;
        __syncthreads();
        part[t] += v;
        __syncthreads();
    }
    int run = (t > 0) ? part[t - 1] : 0;
    for (int i = b; i < e; i++) {
        row_ptr[i] = run;
        cursor[i] = run;
        run += deg[i];
    }
    if (t == 1023) row_ptr[N] = part[1023];
}

__global__ void scatter_k(const int* __restrict__ ei, int E, int N,
                          int* __restrict__ cursor, int* __restrict__ csr_src)
{
    int i = blockIdx.x * blockDim.x + threadIdx.x;
    if (i >= E) return;
    int s = ei[i];
    int d = ei[E + i];
    if ((unsigned)s >= (unsigned)N || (unsigned)d >= (unsigned)N) return;
    int pos = atomicAdd(&cursor[d], 1);
    csr_src[pos] = s;
}

// ================= tf32 tensor-core GEMM + fused attention scores ==========
// C[M,256] = A[M,K] @ B[K,256]; K multiple of 32.
// Epilogue also accumulates a_src/a_dst (pre-zeroed) via atomics.
#define GBM 128
#define GBN 128
#define GBK 32
#define ASTR 36
#define BSTR 136
#define STAGE_F (GBM * ASTR + GBK * BSTR)   // floats per stage = 8960
#define GEMM_SMEM_BYTES (2 * STAGE_F * 4)   // 71680 bytes

__device__ __forceinline__ void gemm_load_tiles(
    float* As, float* Bs, const float* __restrict__ A, const float* __restrict__ B,
    int M, int K, int block_row, int block_col, int k0, int tid)
{
    int r0 = tid >> 3;             // 0..31
    int f4 = (tid & 7) * 4;        // 0..28
#pragma unroll
    for (int i = 0; i < 4; i++) {
        int r = r0 + i * 32;
        int gr = block_row + r;
        if (gr >= M) gr = M - 1;   // clamp: rows >= M never stored
        cp16(&As[r * ASTR + f4], &A[(size_t)gr * K + k0 + f4]);
    }
    int br0 = tid >> 5;            // 0..7
    int bf4 = (tid & 31) * 4;      // 0..124
#pragma unroll
    for (int i = 0; i < 4; i++) {
        int bk = br0 + i * 8;
        cp16(&Bs[bk * BSTR + bf4], &B[(size_t)(k0 + bk) * HCn + block_col + bf4]);
    }
    cp_commit();
}

__global__ __launch_bounds__(256) void gemm_tf32(
    const float* __restrict__ A, const float* __restrict__ B,
    float* __restrict__ C, int M, int K,
    const float* __restrict__ att_s, const float* __restrict__ att_d,
    float* __restrict__ asrc, float* __restrict__ adst)
{
    extern __shared__ float smem[];
    __shared__ float satt_s[GBN], satt_d[GBN];
    const int tid  = threadIdx.x;
    const int lane = tid & 31;
    const int wid  = tid >> 5;
    const int warp_m = wid & 1;
    const int warp_n = wid >> 1;
    const int gid = lane >> 2;
    const int tig = lane & 3;
    const int block_row = blockIdx.y * GBM;
    const int block_col = blockIdx.x * GBN;

    if (tid < GBN) {
        satt_s[tid] = att_s[block_col + tid];
        satt_d[tid] = att_d[block_col + tid];
    }

    float4 acc[4][4];
#pragma unroll
    for (int i = 0; i < 4; i++)
#pragma unroll
        for (int j = 0; j < 4; j++) acc[i][j] = make_float4(0.f, 0.f, 0.f, 0.f);

    const int niter = K / GBK;
    gemm_load_tiles(smem, smem + GBM * ASTR, A, B, M, K, block_row, block_col, 0, tid);

    for (int it = 0; it < niter; it++) {
        int cur = it & 1;
        if (it + 1 < niter) {
            float* As_n = smem + (1 - cur) * STAGE_F;
            gemm_load_tiles(As_n, As_n + GBM * ASTR, A, B, M, K, block_row, block_col,
                            (it + 1) * GBK, tid);
            cp_wait<1>();
        } else {
            cp_wait<0>();
        }
        __syncthreads();

        const float* As = smem + cur * STAGE_F;
        const float* Bs = As + GBM * ASTR;

#pragma unroll
        for (int ks = 0; ks < 4; ks++) {
            int kb = ks * 8;
            uint32_t af[4][4], bf[4][2];
#pragma unroll
            for (int tm = 0; tm < 4; tm++) {
                int row = warp_m * 64 + tm * 16 + gid;
                const float* ap = &As[row * ASTR + kb + tig];
                af[tm][0] = f2tf(ap[0]);
                af[tm][1] = f2tf(ap[8 * ASTR]);
                af[tm][2] = f2tf(ap[4]);
                af[tm][3] = f2tf(ap[8 * ASTR + 4]);
            }
#pragma unroll
            for (int tn = 0; tn < 4; tn++) {
                int col = warp_n * 32 + tn * 8 + gid;
                const float* bp = &Bs[(kb + tig) * BSTR + col];
                bf[tn][0] = f2tf(bp[0]);
                bf[tn][1] = f2tf(bp[4 * BSTR]);
            }
#pragma unroll
            for (int tm = 0; tm < 4; tm++)
#pragma unroll
                for (int tn = 0; tn < 4; tn++)
                    mma_tf32(acc[tm][tn], af[tm][0], af[tm][1], af[tm][2], af[tm][3],
                             bf[tn][0], bf[tn][1]);
        }
        __syncthreads();
    }

    // epilogue: store C + accumulate per-head attention partials
    const int head = (block_col + warp_n * 32) >> 6;   // this warp's 32 cols lie in one head
#pragma unroll
    for (int tm = 0; tm < 4; tm++) {
        int grow0 = block_row + warp_m * 64 + tm * 16 + gid;
        int grow1 = grow0 + 8;
        float s0 = 0.f, s1 = 0.f, d0 = 0.f, d1 = 0.f;
#pragma unroll
        for (int tn = 0; tn < 4; tn++) {
            int lc = warp_n * 32 + tn * 8 + tig * 2;
            float ws0 = satt_s[lc], ws1 = satt_s[lc + 1];
            float wd0 = satt_d[lc], wd1 = satt_d[lc + 1];
            float4 a = acc[tm][tn];
            s0 += ws0 * a.x + ws1 * a.y;
            d0 += wd0 * a.x + wd1 * a.y;
            s1 += ws0 * a.z + ws1 * a.w;
            d1 += wd0 * a.z + wd1 * a.w;
            int gcol = block_col + lc;
            if (grow0 < M)
                *(float2*)&C[(size_t)grow0 * HCn + gcol] = make_float2(a.x, a.y);
            if (grow1 < M)
                *(float2*)&C[(size_t)grow1 * HCn + gcol] = make_float2(a.z, a.w);
        }
        // reduce over the 4 tig lanes of each quad
#pragma unroll
        for (int o = 1; o <= 2; o <<= 1) {
            s0 += __shfl_xor_sync(0xffffffffu, s0, o);
            s1 += __shfl_xor_sync(0xffffffffu, s1, o);
            d0 += __shfl_xor_sync(0xffffffffu, d0, o);
            d1 += __shfl_xor_sync(0xffffffffu, d1, o);
        }
        if (tig == 0) {
            if (grow0 < M) {
                atomicAdd(&asrc[grow0 * Hh + head], s0);
                atomicAdd(&adst[grow0 * Hh + head], d0);
            }
            if (grow1 < M) {
                atomicAdd(&asrc[grow1 * Hh + head], s1);
                atomicAdd(&adst[grow1 * Hh + head], d1);
            }
        }
    }
}

// ======== fused CSR aggregation + softmax + bias + ELU ========
// one warp per destination node; lane owns 8 channels (head = lane>>3).
// CONCAT=true:  out[d, 256] = elu(agg/den + bias)
// CONCAT=false: out[d, 64]  = elu(mean_heads(agg/den) + bias)
template <bool CONCAT>
__global__ __launch_bounds__(256) void gat_agg_csr(
    const int* __restrict__ row_ptr, const int* __restrict__ csr_src,
    const float* __restrict__ asrc, const float* __restrict__ adst,
    const float* __restrict__ h, const float* __restrict__ bias,
    float* __restrict__ out, int N)
{
    __shared__ float sb[HCn];
    int tid = threadIdx.x;
    if (tid < (CONCAT ? HCn : Cc)) sb[tid] = bias[tid];
    __syncthreads();

    int d = blockIdx.x * 8 + (tid >> 5);
    int lane = tid & 31;
    if (d >= N) return;
    int head = lane >> 3;

    float adst_h = adst[d * Hh + head];
    int beg = row_ptr[d], end = row_ptr[d + 1];

    float4 acc0 = make_float4(0.f, 0.f, 0.f, 0.f);
    float4 acc1 = make_float4(0.f, 0.f, 0.f, 0.f);
    float dsum = 0.f;

    for (int k = beg; k <= end; k++) {           // k == end -> self loop
        int s = (k < end) ? csr_src[k] : d;
        float e = lrelu(asrc[s * Hh + head] + adst_h);
        float p = __expf(e);
        dsum += p;
        const float4* hp = (const float4*)&h[(size_t)s * HCn + lane * 8];
        float4 v0 = hp[0], v1 = hp[1];
        acc0.x += p * v0.x; acc0.y += p * v0.y; acc0.z += p * v0.z; acc0.w += p * v0.w;
        acc1.x += p * v1.x; acc1.y += p * v1.y; acc1.z += p * v1.z; acc1.w += p * v1.w;
    }

    float inv = 1.f / dsum;   // identical across the 8 lanes of a head group

    if (CONCAT) {
        int c = lane * 8;
        float4 o0, o1;
        o0.x = elu1(acc0.x * inv + sb[c + 0]);
        o0.y = elu1(acc0.y * inv + sb[c + 1]);
        o0.z = elu1(acc0.z * inv + sb[c + 2]);
        o0.w = elu1(acc0.w * inv + sb[c + 3]);
        o1.x = elu1(acc1.x * inv + sb[c + 4]);
        o1.y = elu1(acc1.y * inv + sb[c + 5]);
        o1.z = elu1(acc1.z * inv + sb[c + 6]);
        o1.w = elu1(acc1.w * inv + sb[c + 7]);
        float4* op = (float4*)&out[(size_t)d * HCn + c];
        op[0] = o0;
        op[1] = o1;
    } else {
        float v[8];
        v[0] = acc0.x * inv; v[1] = acc0.y * inv; v[2] = acc0.z * inv; v[3] = acc0.w * inv;
        v[4] = acc1.x * inv; v[5] = acc1.y * inv; v[6] = acc1.z * inv; v[7] = acc1.w * inv;
        // sum across heads: lanes differing in bits 3,4 hold the same channel
#pragma unroll
        for (int j = 0; j < 8; j++) {
            v[j] += __shfl_xor_sync(0xffffffffu, v[j], 8);
            v[j] += __shfl_xor_sync(0xffffffffu, v[j], 16);
        }
        if (lane < 8) {
            int c = lane * 8;   // channel within 64
            float4 o0, o1;
            o0.x = elu1(v[0] * 0.25f + sb[c + 0]);
            o0.y = elu1(v[1] * 0.25f + sb[c + 1]);
            o0.z = elu1(v[2] * 0.25f + sb[c + 2]);
            o0.w = elu1(v[3] * 0.25f + sb[c + 3]);
            o1.x = elu1(v[4] * 0.25f + sb[c + 4]);
            o1.y = elu1(v[5] * 0.25f + sb[c + 5]);
            o1.z = elu1(v[6] * 0.25f + sb[c + 6]);
            o1.w = elu1(v[7] * 0.25f + sb[c + 7]);
            float4* op = (float4*)&out[(size_t)d * Cc + c];
            op[0] = o0;
            op[1] = o1;
        }
    }
}

// ---------------- pooling ----------------
__global__ void graph_bounds_k(const int* __restrict__ batch, int N,
                               int* __restrict__ start, int* __restrict__ end)
{
    int n = blockIdx.x * blockDim.x + threadIdx.x;
    if (n >= N) return;
    int g = batch[n];
    if (g < 0 || g >= NG) return;
    atomicMin(&start[g], n);
    atomicMax(&end[g], n + 1);
}

__global__ __launch_bounds__(256) void pool_k(
    const float* __restrict__ hf, const int* __restrict__ start,
    const int* __restrict__ end, float* __restrict__ pooled)
{
    int g = blockIdx.x;
    int tid = threadIdx.x;
    int col = tid & 63, sub = tid >> 6;
    int s = start[g], e = end[g];
    if (s > e) { s = 0; e = 0; }
    float acc = 0.f;
    for (int n = s + sub; n < e; n += 4) acc += hf[(size_t)n * Cc + col];
    __shared__ float sm[256];
    sm[tid] = acc;
    __syncthreads();
    if (sub == 0) {
        float v = sm[col] + sm[64 + col] + sm[128 + col] + sm[192 + col];
        float cnt = (e > s) ? (float)(e - s) : 0.f;
        pooled[g * Cc + col] = v / fmaxf(cnt, 1.0f);
    }
}

// ---------------- final head ----------------
__global__ __launch_bounds__(1024) void head_k(
    const float* __restrict__ pooled, const float* __restrict__ Wa,
    const float* __restrict__ ba, float* __restrict__ out)
{
    __shared__ float sW[Cc * NA];
    int t = threadIdx.y * 32 + threadIdx.x;
    for (int i = t; i < Cc * NA; i += 1024) sW[i] = Wa[i];
    __syncthreads();
    int a = threadIdx.x;
#pragma unroll
    for (int rep = 0; rep < 2; rep++) {
        int g = threadIdx.y + rep * 32;
        float acc = ba[a];
#pragma unroll 8
        for (int c = 0; c < Cc; c++) acc = fmaf(pooled[g * Cc + c], sW[c * NA + a], acc);
        out[g * NA + a] = acc;
    }
}

// ---------------- host orchestration ----------------
static float* symf(const void* sym) {
    void* p = nullptr;
    cudaGetSymbolAddress(&p, sym);
    return (float*)p;
}
static int* symi(const void* sym) {
    void* p = nullptr;
    cudaGetSymbolAddress(&p, sym);
    return (int*)p;
}

extern "C" void kernel_launch(void* const* d_in, const int* in_sizes, int n_in,
                              void* d_out, int out_size)
{
    static int smem_set = 0;
    if (!smem_set) {
        cudaFuncSetAttribute(gemm_tf32, cudaFuncAttributeMaxDynamicSharedMemorySize,
                             GEMM_SMEM_BYTES);
        smem_set = 1;
    }

    // -------- robust input mapping (filter size-1 scalar inputs) --------
    const void* t[13];
    int tsz[13];
    int cnt = 0;
    for (int i = 0; i < n_in && cnt < 13; i++) {
        if (in_sizes[i] <= 1) continue;
        t[cnt] = d_in[i];
        tsz[cnt] = in_sizes[i];
        cnt++;
    }
    if (cnt < 13) return;

    const float* x     = (const float*)t[0];
    const int*   ei    = (const int*)t[1];
    const int*   batch = (const int*)t[2];
    const float* W1    = (const float*)t[3];
    const float* attS1 = (const float*)t[4];
    const float* attD1 = (const float*)t[5];
    const float* b1    = (const float*)t[6];
    const float* W2    = (const float*)t[7];
    const float* attS2 = (const float*)t[8];
    const float* attD2 = (const float*)t[9];
    const float* b2    = (const float*)t[10];
    const float* Wa    = (const float*)t[11];
    const float* ba    = (const float*)t[12];

    const int Fin = 128;
    int N = tsz[0] / Fin;
    int E = tsz[1] / 2;
    if (N > MAXN || E > MAXE || N <= 0 || E <= 0) return;

    float* h    = symf(g_h);
    float* h2   = symf(g_h2);
    float* asrc = symf(g_asrc);
    float* adst = symf(g_adst);
    float* hf   = symf(g_hf);
    float* pooled = symf(g_pooled);
    int* gstart = symi(g_start);
    int* gend   = symi(g_end);
    int* rowptr = symi(g_rowptr);
    int* cursor = symi(g_cursor);
    int* csr    = symi(g_csr);

    // ---- CSR build (reused by both layers). deg stored in cursor temporarily ----
    zero_deg_k<<<(N + 255) / 256, 256>>>(cursor, N);
    count_k<<<(E + 255) / 256, 256>>>(ei, E, N, cursor);
    // scan reads deg from cursor's current contents; write row_ptr and reset cursor
    {
        // copy deg out of cursor via scan's read-before-write pattern:
        // scan_k(deg=cursor_in, row_ptr, cursor_out) — reads then overwrites; safe because
        // each thread reads its chunk fully before writing it (same ranges).
        scan_k<<<1, 1024>>>(cursor, rowptr, cursor, N);
    }
    scatter_k<<<(E + 255) / 256, 256>>>(ei, E, N, cursor, csr);

    dim3 gemm_grid(HCn / GBN, (N + GBM - 1) / GBM);
    unsigned agg_grid = (unsigned)((N + 7) / 8);
    int nh = N * Hh;

    // ---- layer 1 ----
    zero_attn_k<<<(nh + 255) / 256, 256>>>(asrc, adst, nh);
    gemm_tf32<<<gemm_grid, 256, GEMM_SMEM_BYTES>>>(x, W1, h, N, Fin, attS1, attD1, asrc, adst);
    gat_agg_csr<true><<<agg_grid, 256>>>(rowptr, csr, asrc, adst, h, b1, h2, N);

    // ---- layer 2 ----
    zero_attn_k<<<(nh + 255) / 256, 256>>>(asrc, adst, nh);
    gemm_tf32<<<gemm_grid, 256, GEMM_SMEM_BYTES>>>(h2, W2, h, N, HCn, attS2, attD2, asrc, adst);
    gat_agg_csr<false><<<agg_grid, 256>>>(rowptr, csr, asrc, adst, h, b2, hf, N);

    // ---- pooling ----
    init_bounds_k<<<1, 64>>>(gstart, gend);
    fill_f32<<<(NG * Cc + 255) / 256, 256>>>(pooled, NG * Cc, 0.f);
    graph_bounds_k<<<(N + 255) / 256, 256>>>(batch, N, gstart, gend);
    pool_k<<<NG, 256>>>(hf, gstart, gend, pooled);

    // ---- head ----
    head_k<<<1, dim3(32, 32)>>>(pooled, Wa, ba, (float*)d_out);
}

// round 7
// speedup vs baseline: 2.7659x; 1.1153x over previous
#include <cuda_runtime.h>
#include <cuda_fp16.h>
#include <math.h>
#include <stdio.h>
#include <stdint.h>

// ---------------- static problem capacities ----------------
#define MAXN 50000
#define MAXE 800000
#define HCn  256      // H*C
#define Hh   4
#define Cc   64
#define NG   64       // graphs
#define NA   32       // actions

// ---------------- device scratch (allocation-free rule) ----------------
__device__ __half g_h [(size_t)MAXN * HCn];   // gemm output in fp16 (gather-only use)
__device__ float g_h2 [(size_t)MAXN * HCn];   // layer-1 output / layer-2 input (fp32)
__device__ float g_asrc[MAXN * Hh];
__device__ float g_adst[MAXN * Hh];
__device__ float g_hf  [(size_t)MAXN * Cc];   // final node features [N,64]
__device__ float g_pooled[NG * Cc];
__device__ int   g_start[NG];
__device__ int   g_end  [NG];
__device__ int   g_rowptr[MAXN + 1];
__device__ int   g_cursor[MAXN];
__device__ int   g_csr[MAXE];

// ---------------- helpers ----------------
__device__ __forceinline__ float lrelu(float x) { return fmaxf(x, 0.2f * x); }
__device__ __forceinline__ float elu1(float x)  { return x > 0.f ? x : expm1f(x); }

__device__ __forceinline__ uint32_t f2tf(float f) {
    uint32_t r;
    asm("cvt.rna.tf32.f32 %0, %1;" : "=r"(r) : "f"(f));
    return r;
}

__device__ __forceinline__ void mma_tf32(float4& c,
    uint32_t a0, uint32_t a1, uint32_t a2, uint32_t a3,
    uint32_t b0, uint32_t b1)
{
    asm volatile(
        "mma.sync.aligned.m16n8k8.row.col.f32.tf32.tf32.f32 "
        "{%0,%1,%2,%3}, {%4,%5,%6,%7}, {%8,%9}, {%0,%1,%2,%3};"
        : "+f"(c.x), "+f"(c.y), "+f"(c.z), "+f"(c.w)
        : "r"(a0), "r"(a1), "r"(a2), "r"(a3), "r"(b0), "r"(b1));
}

__device__ __forceinline__ void cp16(void* sm, const void* gm) {
    uint32_t sa = (uint32_t)__cvta_generic_to_shared(sm);
    asm volatile("cp.async.ca.shared.global [%0], [%1], 16;" :: "r"(sa), "l"(gm));
}
__device__ __forceinline__ void cp_commit() {
    asm volatile("cp.async.commit_group;" ::: "memory");
}
template <int Npend>
__device__ __forceinline__ void cp_wait() {
    asm volatile("cp.async.wait_group %0;" :: "n"(Npend) : "memory");
}

// ---------------- small utility kernels ----------------
__global__ void fill_f32(float* p, size_t n, float v) {
    size_t i = (size_t)blockIdx.x * blockDim.x + threadIdx.x;
    if (i < n) p[i] = v;
}

__global__ void zero_attn_k(float* a, float* b, int n) {
    int i = blockIdx.x * blockDim.x + threadIdx.x;
    if (i < n) { a[i] = 0.f; b[i] = 0.f; }
}

__global__ void init_bounds_k(int* start, int* end) {
    int i = threadIdx.x;
    if (i < NG) { start[i] = 1 << 30; end[i] = 0; }
}

// ---------------- CSR build (by destination) ----------------
__global__ void zero_deg_k(int* deg, int n) {
    int i = blockIdx.x * blockDim.x + threadIdx.x;
    if (i < n) deg[i] = 0;
}

__global__ void count_k(const int* __restrict__ ei, int E, int N, int* __restrict__ deg) {
    int i = blockIdx.x * blockDim.x + threadIdx.x;
    if (i >= E) return;
    int d = ei[E + i];
    if ((unsigned)d < (unsigned)N) atomicAdd(&deg[d], 1);
}

// single block of 1024 threads: exclusive scan of deg[0..N) -> row_ptr, cursor
__global__ __launch_bounds__(1024) void scan_k(
    const int* __restrict__ deg, int* __restrict__ row_ptr,
    int* __restrict__ cursor, int N)
{
    __shared__ int part[1024];
    int t = threadIdx.x;
    int chunk = (N + 1023) / 1024;
    int b = t * chunk, e = min(b + chunk, N);
    int sum = 0;
    for (int i = b; i < e; i++) sum += deg[i];
    part[t] = sum;
    __syncthreads();
    for (int off = 1; off < 1024; off <<= 1) {
        int v = (t >= off) ? part[t - off] : 0;
        __syncthreads();
        part[t] += v;
        __syncthreads();
    }
    int run = (t > 0) ? part[t - 1] : 0;
    for (int i = b; i < e; i++) {
        row_ptr[i] = run;
        cursor[i] = run;
        run += deg[i];
    }
    if (t == 1023) row_ptr[N] = part[1023];
}

__global__ void scatter_k(const int* __restrict__ ei, int E, int N,
                          int* __restrict__ cursor, int* __restrict__ csr_src)
{
    int i = blockIdx.x * blockDim.x + threadIdx.x;
    if (i >= E) return;
    int s = ei[i];
    int d = ei[E + i];
    if ((unsigned)s >= (unsigned)N || (unsigned)d >= (unsigned)N) return;
    int pos = atomicAdd(&cursor[d], 1);
    csr_src[pos] = s;
}

// ================= tf32 tensor-core GEMM + fused attention scores ==========
// C[M,256] = A[M,K] @ B[K,256] stored as fp16; K multiple of 32.
// Epilogue also accumulates a_src/a_dst (pre-zeroed) via atomics (fp32 accums).
#define GBM 128
#define GBN 128
#define GBK 32
#define ASTR 36
#define BSTR 136
#define STAGE_F (GBM * ASTR + GBK * BSTR)   // floats per stage = 8960
#define GEMM_SMEM_BYTES (2 * STAGE_F * 4)   // 71680 bytes

__device__ __forceinline__ void gemm_load_tiles(
    float* As, float* Bs, const float* __restrict__ A, const float* __restrict__ B,
    int M, int K, int block_row, int block_col, int k0, int tid)
{
    int r0 = tid >> 3;             // 0..31
    int f4 = (tid & 7) * 4;        // 0..28
#pragma unroll
    for (int i = 0; i < 4; i++) {
        int r = r0 + i * 32;
        int gr = block_row + r;
        if (gr >= M) gr = M - 1;   // clamp: rows >= M never stored
        cp16(&As[r * ASTR + f4], &A[(size_t)gr * K + k0 + f4]);
    }
    int br0 = tid >> 5;            // 0..7
    int bf4 = (tid & 31) * 4;      // 0..124
#pragma unroll
    for (int i = 0; i < 4; i++) {
        int bk = br0 + i * 8;
        cp16(&Bs[bk * BSTR + bf4], &B[(size_t)(k0 + bk) * HCn + block_col + bf4]);
    }
    cp_commit();
}

__global__ __launch_bounds__(256) void gemm_tf32(
    const float* __restrict__ A, const float* __restrict__ B,
    __half* __restrict__ C, int M, int K,
    const float* __restrict__ att_s, const float* __restrict__ att_d,
    float* __restrict__ asrc, float* __restrict__ adst)
{
    extern __shared__ float smem[];
    __shared__ float satt_s[GBN], satt_d[GBN];
    const int tid  = threadIdx.x;
    const int lane = tid & 31;
    const int wid  = tid >> 5;
    const int warp_m = wid & 1;
    const int warp_n = wid >> 1;
    const int gid = lane >> 2;
    const int tig = lane & 3;
    const int block_row = blockIdx.y * GBM;
    const int block_col = blockIdx.x * GBN;

    if (tid < GBN) {
        satt_s[tid] = att_s[block_col + tid];
        satt_d[tid] = att_d[block_col + tid];
    }

    float4 acc[4][4];
#pragma unroll
    for (int i = 0; i < 4; i++)
#pragma unroll
        for (int j = 0; j < 4; j++) acc[i][j] = make_float4(0.f, 0.f, 0.f, 0.f);

    const int niter = K / GBK;
    gemm_load_tiles(smem, smem + GBM * ASTR, A, B, M, K, block_row, block_col, 0, tid);

    for (int it = 0; it < niter; it++) {
        int cur = it & 1;
        if (it + 1 < niter) {
            float* As_n = smem + (1 - cur) * STAGE_F;
            gemm_load_tiles(As_n, As_n + GBM * ASTR, A, B, M, K, block_row, block_col,
                            (it + 1) * GBK, tid);
            cp_wait<1>();
        } else {
            cp_wait<0>();
        }
        __syncthreads();

        const float* As = smem + cur * STAGE_F;
        const float* Bs = As + GBM * ASTR;

#pragma unroll
        for (int ks = 0; ks < 4; ks++) {
            int kb = ks * 8;
            uint32_t af[4][4], bf[4][2];
#pragma unroll
            for (int tm = 0; tm < 4; tm++) {
                int row = warp_m * 64 + tm * 16 + gid;
                const float* ap = &As[row * ASTR + kb + tig];
                af[tm][0] = f2tf(ap[0]);
                af[tm][1] = f2tf(ap[8 * ASTR]);
                af[tm][2] = f2tf(ap[4]);
                af[tm][3] = f2tf(ap[8 * ASTR + 4]);
            }
#pragma unroll
            for (int tn = 0; tn < 4; tn++) {
                int col = warp_n * 32 + tn * 8 + gid;
                const float* bp = &Bs[(kb + tig) * BSTR + col];
                bf[tn][0] = f2tf(bp[0]);
                bf[tn][1] = f2tf(bp[4 * BSTR]);
            }
#pragma unroll
            for (int tm = 0; tm < 4; tm++)
#pragma unroll
                for (int tn = 0; tn < 4; tn++)
                    mma_tf32(acc[tm][tn], af[tm][0], af[tm][1], af[tm][2], af[tm][3],
                             bf[tn][0], bf[tn][1]);
        }
        __syncthreads();
    }

    // epilogue: store C (fp16) + accumulate per-head attention partials (fp32)
    const int head = (block_col + warp_n * 32) >> 6;   // warp's 32 cols lie in one head
#pragma unroll
    for (int tm = 0; tm < 4; tm++) {
        int grow0 = block_row + warp_m * 64 + tm * 16 + gid;
        int grow1 = grow0 + 8;
        float s0 = 0.f, s1 = 0.f, d0 = 0.f, d1 = 0.f;
#pragma unroll
        for (int tn = 0; tn < 4; tn++) {
            int lc = warp_n * 32 + tn * 8 + tig * 2;
            float ws0 = satt_s[lc], ws1 = satt_s[lc + 1];
            float wd0 = satt_d[lc], wd1 = satt_d[lc + 1];
            float4 a = acc[tm][tn];
            s0 += ws0 * a.x + ws1 * a.y;
            d0 += wd0 * a.x + wd1 * a.y;
            s1 += ws0 * a.z + ws1 * a.w;
            d1 += wd0 * a.z + wd1 * a.w;
            int gcol = block_col + lc;
            if (grow0 < M)
                *(__half2*)&C[(size_t)grow0 * HCn + gcol] = __floats2half2_rn(a.x, a.y);
            if (grow1 < M)
                *(__half2*)&C[(size_t)grow1 * HCn + gcol] = __floats2half2_rn(a.z, a.w);
        }
#pragma unroll
        for (int o = 1; o <= 2; o <<= 1) {
            s0 += __shfl_xor_sync(0xffffffffu, s0, o);
            s1 += __shfl_xor_sync(0xffffffffu, s1, o);
            d0 += __shfl_xor_sync(0xffffffffu, d0, o);
            d1 += __shfl_xor_sync(0xffffffffu, d1, o);
        }
        if (tig == 0) {
            if (grow0 < M) {
                atomicAdd(&asrc[grow0 * Hh + head], s0);
                atomicAdd(&adst[grow0 * Hh + head], d0);
            }
            if (grow1 < M) {
                atomicAdd(&asrc[grow1 * Hh + head], s1);
                atomicAdd(&adst[grow1 * Hh + head], d1);
            }
        }
    }
}

// ======== fused CSR aggregation + softmax + bias + ELU (fp16 gather) ========
// one warp per destination node; lane owns 8 channels (head = lane>>3).
// Software-pipelined: next edge's index/score/row loaded before current FMAs.
template <bool CONCAT>
__global__ __launch_bounds__(256) void gat_agg_csr(
    const int* __restrict__ row_ptr, const int* __restrict__ csr_src,
    const float* __restrict__ asrc, const float* __restrict__ adst,
    const __half* __restrict__ h, const float* __restrict__ bias,
    float* __restrict__ out, int N)
{
    __shared__ float sb[HCn];
    int tid = threadIdx.x;
    if (tid < (CONCAT ? HCn : Cc)) sb[tid] = bias[tid];
    __syncthreads();

    int d = blockIdx.x * 8 + (tid >> 5);
    int lane = tid & 31;
    if (d >= N) return;
    int head = lane >> 3;

    float adst_h = adst[d * Hh + head];
    int beg = row_ptr[d], end = row_ptr[d + 1];

    float4 acc0 = make_float4(0.f, 0.f, 0.f, 0.f);
    float4 acc1 = make_float4(0.f, 0.f, 0.f, 0.f);
    float dsum = 0.f;

    // pipeline stage 0
    int   s_cur = (beg < end) ? csr_src[beg] : d;
    float a_cur = asrc[s_cur * Hh + head];
    uint4 r_cur = *(const uint4*)&h[(size_t)s_cur * HCn + lane * 8];

    for (int k = beg; k <= end; k++) {           // k == end -> self loop
        // prefetch next
        int s_nxt = (k + 1 < end) ? csr_src[k + 1] : d;
        float a_nxt = asrc[s_nxt * Hh + head];
        uint4 r_nxt = *(const uint4*)&h[(size_t)s_nxt * HCn + lane * 8];

        float p = __expf(lrelu(a_cur + adst_h));
        dsum += p;
        const __half2* hh = (const __half2*)&r_cur;
        float2 f0 = __half22float2(hh[0]);
        float2 f1 = __half22float2(hh[1]);
        float2 f2 = __half22float2(hh[2]);
        float2 f3 = __half22float2(hh[3]);
        acc0.x += p * f0.x; acc0.y += p * f0.y; acc0.z += p * f1.x; acc0.w += p * f1.y;
        acc1.x += p * f2.x; acc1.y += p * f2.y; acc1.z += p * f3.x; acc1.w += p * f3.y;

        s_cur = s_nxt; a_cur = a_nxt; r_cur = r_nxt;
    }

    float inv = 1.f / dsum;   // identical across the 8 lanes of a head group

    if (CONCAT) {
        int c = lane * 8;
        float4 o0, o1;
        o0.x = elu1(acc0.x * inv + sb[c + 0]);
        o0.y = elu1(acc0.y * inv + sb[c + 1]);
        o0.z = elu1(acc0.z * inv + sb[c + 2]);
        o0.w = elu1(acc0.w * inv + sb[c + 3]);
        o1.x = elu1(acc1.x * inv + sb[c + 4]);
        o1.y = elu1(acc1.y * inv + sb[c + 5]);
        o1.z = elu1(acc1.z * inv + sb[c + 6]);
        o1.w = elu1(acc1.w * inv + sb[c + 7]);
        float4* op = (float4*)&out[(size_t)d * HCn + c];
        op[0] = o0;
        op[1] = o1;
    } else {
        float v[8];
        v[0] = acc0.x * inv; v[1] = acc0.y * inv; v[2] = acc0.z * inv; v[3] = acc0.w * inv;
        v[4] = acc1.x * inv; v[5] = acc1.y * inv; v[6] = acc1.z * inv; v[7] = acc1.w * inv;
#pragma unroll
        for (int j = 0; j < 8; j++) {
            v[j] += __shfl_xor_sync(0xffffffffu, v[j], 8);
            v[j] += __shfl_xor_sync(0xffffffffu, v[j], 16);
        }
        if (lane < 8) {
            int c = lane * 8;
            float4 o0, o1;
            o0.x = elu1(v[0] * 0.25f + sb[c + 0]);
            o0.y = elu1(v[1] * 0.25f + sb[c + 1]);
            o0.z = elu1(v[2] * 0.25f + sb[c + 2]);
            o0.w = elu1(v[3] * 0.25f + sb[c + 3]);
            o1.x = elu1(v[4] * 0.25f + sb[c + 4]);
            o1.y = elu1(v[5] * 0.25f + sb[c + 5]);
            o1.z = elu1(v[6] * 0.25f + sb[c + 6]);
            o1.w = elu1(v[7] * 0.25f + sb[c + 7]);
            float4* op = (float4*)&out[(size_t)d * Cc + c];
            op[0] = o0;
            op[1] = o1;
        }
    }
}

// ---------------- pooling ----------------
__global__ void graph_bounds_k(const int* __restrict__ batch, int N,
                               int* __restrict__ start, int* __restrict__ end)
{
    int n = blockIdx.x * blockDim.x + threadIdx.x;
    if (n >= N) return;
    int g = batch[n];
    if (g < 0 || g >= NG) return;
    atomicMin(&start[g], n);
    atomicMax(&end[g], n + 1);
}

__global__ __launch_bounds__(256) void pool_k(
    const float* __restrict__ hf, const int* __restrict__ start,
    const int* __restrict__ end, float* __restrict__ pooled)
{
    int g = blockIdx.x;
    int tid = threadIdx.x;
    int col = tid & 63, sub = tid >> 6;
    int s = start[g], e = end[g];
    if (s > e) { s = 0; e = 0; }
    float acc = 0.f;
    for (int n = s + sub; n < e; n += 4) acc += hf[(size_t)n * Cc + col];
    __shared__ float sm[256];
    sm[tid] = acc;
    __syncthreads();
    if (sub == 0) {
        float v = sm[col] + sm[64 + col] + sm[128 + col] + sm[192 + col];
        float cnt = (e > s) ? (float)(e - s) : 0.f;
        pooled[g * Cc + col] = v / fmaxf(cnt, 1.0f);
    }
}

// ---------------- final head ----------------
__global__ __launch_bounds__(1024) void head_k(
    const float* __restrict__ pooled, const float* __restrict__ Wa,
    const float* __restrict__ ba, float* __restrict__ out)
{
    __shared__ float sW[Cc * NA];
    int t = threadIdx.y * 32 + threadIdx.x;
    for (int i = t; i < Cc * NA; i += 1024) sW[i] = Wa[i];
    __syncthreads();
    int a = threadIdx.x;
#pragma unroll
    for (int rep = 0; rep < 2; rep++) {
        int g = threadIdx.y + rep * 32;
        float acc = ba[a];
#pragma unroll 8
        for (int c = 0; c < Cc; c++) acc = fmaf(pooled[g * Cc + c], sW[c * NA + a], acc);
        out[g * NA + a] = acc;
    }
}

// ---------------- host orchestration ----------------
static void* symp(const void* sym) {
    void* p = nullptr;
    cudaGetSymbolAddress(&p, sym);
    return p;
}

extern "C" void kernel_launch(void* const* d_in, const int* in_sizes, int n_in,
                              void* d_out, int out_size)
{
    static int smem_set = 0;
    if (!smem_set) {
        cudaFuncSetAttribute(gemm_tf32, cudaFuncAttributeMaxDynamicSharedMemorySize,
                             GEMM_SMEM_BYTES);
        smem_set = 1;
    }

    // -------- robust input mapping (filter size-1 scalar inputs) --------
    const void* t[13];
    int tsz[13];
    int cnt = 0;
    for (int i = 0; i < n_in && cnt < 13; i++) {
        if (in_sizes[i] <= 1) continue;
        t[cnt] = d_in[i];
        tsz[cnt] = in_sizes[i];
        cnt++;
    }
    if (cnt < 13) return;

    const float* x     = (const float*)t[0];
    const int*   ei    = (const int*)t[1];
    const int*   batch = (const int*)t[2];
    const float* W1    = (const float*)t[3];
    const float* attS1 = (const float*)t[4];
    const float* attD1 = (const float*)t[5];
    const float* b1    = (const float*)t[6];
    const float* W2    = (const float*)t[7];
    const float* attS2 = (const float*)t[8];
    const float* attD2 = (const float*)t[9];
    const float* b2    = (const float*)t[10];
    const float* Wa    = (const float*)t[11];
    const float* ba    = (const float*)t[12];

    const int Fin = 128;
    int N = tsz[0] / Fin;
    int E = tsz[1] / 2;
    if (N > MAXN || E > MAXE || N <= 0 || E <= 0) return;

    __half* h   = (__half*)symp(g_h);
    float* h2   = (float*)symp(g_h2);
    float* asrc = (float*)symp(g_asrc);
    float* adst = (float*)symp(g_adst);
    float* hf   = (float*)symp(g_hf);
    float* pooled = (float*)symp(g_pooled);
    int* gstart = (int*)symp(g_start);
    int* gend   = (int*)symp(g_end);
    int* rowptr = (int*)symp(g_rowptr);
    int* cursor = (int*)symp(g_cursor);
    int* csr    = (int*)symp(g_csr);

    // ---- CSR build (reused by both layers) ----
    zero_deg_k<<<(N + 255) / 256, 256>>>(cursor, N);
    count_k<<<(E + 255) / 256, 256>>>(ei, E, N, cursor);
    scan_k<<<1, 1024>>>(cursor, rowptr, cursor, N);
    scatter_k<<<(E + 255) / 256, 256>>>(ei, E, N, cursor, csr);

    dim3 gemm_grid(HCn / GBN, (N + GBM - 1) / GBM);
    unsigned agg_grid = (unsigned)((N + 7) / 8);
    int nh = N * Hh;

    // ---- layer 1 ----
    zero_attn_k<<<(nh + 255) / 256, 256>>>(asrc, adst, nh);
    gemm_tf32<<<gemm_grid, 256, GEMM_SMEM_BYTES>>>(x, W1, h, N, Fin, attS1, attD1, asrc, adst);
    gat_agg_csr<true><<<agg_grid, 256>>>(rowptr, csr, asrc, adst, h, b1, h2, N);

    // ---- layer 2 ----
    zero_attn_k<<<(nh + 255) / 256, 256>>>(asrc, adst, nh);
    gemm_tf32<<<gemm_grid, 256, GEMM_SMEM_BYTES>>>(h2, W2, h, N, HCn, attS2, attD2, asrc, adst);
    gat_agg_csr<false><<<agg_grid, 256>>>(rowptr, csr, asrc, adst, h, b2, hf, N);

    // ---- pooling ----
    init_bounds_k<<<1, 64>>>(gstart, gend);
    fill_f32<<<(NG * Cc + 255) / 256, 256>>>(pooled, NG * Cc, 0.f);
    graph_bounds_k<<<(N + 255) / 256, 256>>>(batch, N, gstart, gend);
    pool_k<<<NG, 256>>>(hf, gstart, gend, pooled);

    // ---- head ----
    head_k<<<1, dim3(32, 32)>>>(pooled, Wa, ba, (float*)d_out);
}

// round 8
// speedup vs baseline: 2.8634x; 1.0353x over previous
#include <cuda_runtime.h>
#include <cuda_fp16.h>
#include <math.h>
#include <stdio.h>
#include <stdint.h>

// ---------------- static problem capacities ----------------
#define MAXN 50000
#define MAXE 800000
#define HCn  256      // H*C
#define Hh   4
#define Cc   64
#define NG   64       // graphs
#define NA   32       // actions

// ---------------- device scratch (allocation-free rule) ----------------
__device__ __half g_ah[(size_t)MAXN * HCn];   // GEMM A input: x fp16, then h2 fp16
__device__ __half g_h [(size_t)MAXN * HCn];   // GEMM output (gather source)
__device__ __half g_w1t[256 * 128];           // W1^T fp16  [n][k]
__device__ __half g_w2t[256 * 256];           // W2^T fp16  [n][k]
__device__ float g_asrc[MAXN * Hh];
__device__ float g_adst[MAXN * Hh];
__device__ float g_hf  [(size_t)MAXN * Cc];   // final node features [N,64]
__device__ float g_pooled[NG * Cc];
__device__ int   g_start[NG];
__device__ int   g_end  [NG];
__device__ int   g_rowptr[MAXN + 1];
__device__ int   g_cursor[MAXN];
__device__ int   g_csr[MAXE];

// ---------------- helpers ----------------
__device__ __forceinline__ float lrelu(float x) { return fmaxf(x, 0.2f * x); }
__device__ __forceinline__ float elu1(float x)  { return x > 0.f ? x : expm1f(x); }

__device__ __forceinline__ void mma_f16(float4& c,
    uint32_t a0, uint32_t a1, uint32_t a2, uint32_t a3,
    uint32_t b0, uint32_t b1)
{
    asm volatile(
        "mma.sync.aligned.m16n8k16.row.col.f32.f16.f16.f32 "
        "{%0,%1,%2,%3}, {%4,%5,%6,%7}, {%8,%9}, {%0,%1,%2,%3};"
        : "+f"(c.x), "+f"(c.y), "+f"(c.z), "+f"(c.w)
        : "r"(a0), "r"(a1), "r"(a2), "r"(a3), "r"(b0), "r"(b1));
}

__device__ __forceinline__ void cp16(void* sm, const void* gm) {
    uint32_t sa = (uint32_t)__cvta_generic_to_shared(sm);
    asm volatile("cp.async.ca.shared.global [%0], [%1], 16;" :: "r"(sa), "l"(gm));
}
__device__ __forceinline__ void cp_commit() {
    asm volatile("cp.async.commit_group;" ::: "memory");
}
template <int Npend>
__device__ __forceinline__ void cp_wait() {
    asm volatile("cp.async.wait_group %0;" :: "n"(Npend) : "memory");
}

// ---------------- small utility kernels ----------------
__global__ void fill_f32(float* p, size_t n, float v) {
    size_t i = (size_t)blockIdx.x * blockDim.x + threadIdx.x;
    if (i < n) p[i] = v;
}

__global__ void zero_attn_k(float* a, float* b, int n) {
    int i = blockIdx.x * blockDim.x + threadIdx.x;
    if (i < n) { a[i] = 0.f; b[i] = 0.f; }
}

__global__ void init_bounds_k(int* start, int* end) {
    int i = threadIdx.x;
    if (i < NG) { start[i] = 1 << 30; end[i] = 0; }
}

// x (fp32) -> fp16, vectorized 4-wide
__global__ void convert_x_k(const float* __restrict__ x, __half* __restrict__ xh, size_t n4) {
    size_t i = (size_t)blockIdx.x * blockDim.x + threadIdx.x;
    if (i >= n4) return;
    float4 v = ((const float4*)x)[i];
    __half2 h0 = __floats2half2_rn(v.x, v.y);
    __half2 h1 = __floats2half2_rn(v.z, v.w);
    ((__half2*)xh)[i * 2]     = h0;
    ((__half2*)xh)[i * 2 + 1] = h1;
}

// W [K][256] fp32 -> Wt [256][K] fp16
__global__ void convert_wt_k(const float* __restrict__ W, __half* __restrict__ Wt, int K) {
    int idx = blockIdx.x * blockDim.x + threadIdx.x;
    if (idx >= K * 256) return;
    int k = idx >> 8;
    int n = idx & 255;
    Wt[n * K + k] = __float2half(W[idx]);
}

// ---------------- CSR build (by destination) ----------------
__global__ void zero_deg_k(int* deg, int n) {
    int i = blockIdx.x * blockDim.x + threadIdx.x;
    if (i < n) deg[i] = 0;
}

__global__ void count_k(const int* __restrict__ ei, int E, int N, int* __restrict__ deg) {
    int i = blockIdx.x * blockDim.x + threadIdx.x;
    if (i >= E) return;
    int d = ei[E + i];
    if ((unsigned)d < (unsigned)N) atomicAdd(&deg[d], 1);
}

__global__ __launch_bounds__(1024) void scan_k(
    const int* __restrict__ deg, int* __restrict__ row_ptr,
    int* __restrict__ cursor, int N)
{
    __shared__ int part[1024];
    int t = threadIdx.x;
    int chunk = (N + 1023) / 1024;
    int b = t * chunk, e = min(b + chunk, N);
    int sum = 0;
    for (int i = b; i < e; i++) sum += deg[i];
    part[t] = sum;
    __syncthreads();
    for (int off = 1; off < 1024; off <<= 1) {
        int v = (t >= off) ? part[t - off] : 0;
        __syncthreads();
        part[t] += v;
        __syncthreads();
    }
    int run = (t > 0) ? part[t - 1] : 0;
    for (int i = b; i < e; i++) {
        row_ptr[i] = run;
        cursor[i] = run;
        run += deg[i];
    }
    if (t == 1023) row_ptr[N] = part[1023];
}

__global__ void scatter_k(const int* __restrict__ ei, int E, int N,
                          int* __restrict__ cursor, int* __restrict__ csr_src)
{
    int i = blockIdx.x * blockDim.x + threadIdx.x;
    if (i >= E) return;
    int s = ei[i];
    int d = ei[E + i];
    if ((unsigned)s >= (unsigned)N || (unsigned)d >= (unsigned)N) return;
    int pos = atomicAdd(&cursor[d], 1);
    csr_src[pos] = s;
}

// ================= fp16 tensor-core GEMM + fused attention scores ==========
// C[M,256] = A[M,K] @ Bt[256,K]^T stored fp16; K multiple of 32.
// A [M][K] fp16 row-major, Bt [256][K] fp16 (weights transposed).
// Epilogue accumulates a_src/a_dst (pre-zeroed) via atomics, fp32.
#define GBM 128
#define GBN 128
#define GBK 32
#define HSTR 40                              // halfs per smem row (bank-conflict-free)
#define STAGE_H (2 * GBM * HSTR)             // halfs per stage (A tile + B tile) = 10240
#define GEMM_SMEM_BYTES (2 * STAGE_H * 2)    // 40960 bytes

__device__ __forceinline__ void gemm_load_tiles(
    __half* As, __half* Bs, const __half* __restrict__ A, const __half* __restrict__ Bt,
    int M, int K, int block_row, int block_col, int k0, int tid)
{
    // A tile: 128 rows x 32 halfs = 512 16B-chunks; 2 per thread
#pragma unroll
    for (int i = 0; i < 2; i++) {
        int idx = tid * 2 + i;            // 0..511
        int r   = idx >> 2;               // 0..127
        int c   = (idx & 3) * 8;          // 0,8,16,24 (halfs)
        int gr = block_row + r;
        if (gr >= M) gr = M - 1;          // clamp: rows >= M never stored
        cp16(&As[r * HSTR + c], &A[(size_t)gr * K + k0 + c]);
    }
    // B tile: 128 n-rows x 32 halfs from Bt
#pragma unroll
    for (int i = 0; i < 2; i++) {
        int idx = tid * 2 + i;
        int r   = idx >> 2;
        int c   = (idx & 3) * 8;
        cp16(&Bs[r * HSTR + c], &Bt[(size_t)(block_col + r) * K + k0 + c]);
    }
    cp_commit();
}

__global__ __launch_bounds__(256) void gemm_f16(
    const __half* __restrict__ A, const __half* __restrict__ Bt,
    __half* __restrict__ C, int M, int K,
    const float* __restrict__ att_s, const float* __restrict__ att_d,
    float* __restrict__ asrc, float* __restrict__ adst)
{
    extern __shared__ __half smem[];
    __shared__ float satt_s[GBN], satt_d[GBN];
    const int tid  = threadIdx.x;
    const int lane = tid & 31;
    const int wid  = tid >> 5;
    const int warp_m = wid & 1;
    const int warp_n = wid >> 1;
    const int gid = lane >> 2;
    const int tig = lane & 3;
    const int block_row = blockIdx.y * GBM;
    const int block_col = blockIdx.x * GBN;

    if (tid < GBN) {
        satt_s[tid] = att_s[block_col + tid];
        satt_d[tid] = att_d[block_col + tid];
    }

    float4 acc[4][4];
#pragma unroll
    for (int i = 0; i < 4; i++)
#pragma unroll
        for (int j = 0; j < 4; j++) acc[i][j] = make_float4(0.f, 0.f, 0.f, 0.f);

    const int niter = K / GBK;
    gemm_load_tiles(smem, smem + GBM * HSTR, A, Bt, M, K, block_row, block_col, 0, tid);

    for (int it = 0; it < niter; it++) {
        int cur = it & 1;
        if (it + 1 < niter) {
            __half* As_n = smem + (1 - cur) * STAGE_H;
            gemm_load_tiles(As_n, As_n + GBM * HSTR, A, Bt, M, K, block_row, block_col,
                            (it + 1) * GBK, tid);
            cp_wait<1>();
        } else {
            cp_wait<0>();
        }
        __syncthreads();

        const __half* As = smem + cur * STAGE_H;
        const __half* Bs = As + GBM * HSTR;

#pragma unroll
        for (int ks = 0; ks < 2; ks++) {        // two k16 steps per GBK=32
            int kb = ks * 16;
            uint32_t af[4][4], bf[4][2];
#pragma unroll
            for (int tm = 0; tm < 4; tm++) {
                int row = warp_m * 64 + tm * 16 + gid;
                const __half* ap = &As[row * HSTR + kb + 2 * tig];
                af[tm][0] = *(const uint32_t*)ap;
                af[tm][1] = *(const uint32_t*)(ap + 8 * HSTR);
                af[tm][2] = *(const uint32_t*)(ap + 8);
                af[tm][3] = *(const uint32_t*)(ap + 8 * HSTR + 8);
            }
#pragma unroll
            for (int tn = 0; tn < 4; tn++) {
                int col = warp_n * 32 + tn * 8 + gid;
                const __half* bp = &Bs[col * HSTR + kb + 2 * tig];
                bf[tn][0] = *(const uint32_t*)bp;
                bf[tn][1] = *(const uint32_t*)(bp + 8);
            }
#pragma unroll
            for (int tm = 0; tm < 4; tm++)
#pragma unroll
                for (int tn = 0; tn < 4; tn++)
                    mma_f16(acc[tm][tn], af[tm][0], af[tm][1], af[tm][2], af[tm][3],
                            bf[tn][0], bf[tn][1]);
        }
        __syncthreads();
    }

    // epilogue: store C (fp16) + accumulate per-head attention partials (fp32)
    const int head = (block_col + warp_n * 32) >> 6;   // warp's 32 cols lie in one head
#pragma unroll
    for (int tm = 0; tm < 4; tm++) {
        int grow0 = block_row + warp_m * 64 + tm * 16 + gid;
        int grow1 = grow0 + 8;
        float s0 = 0.f, s1 = 0.f, d0 = 0.f, d1 = 0.f;
#pragma unroll
        for (int tn = 0; tn < 4; tn++) {
            int lc = warp_n * 32 + tn * 8 + tig * 2;
            float ws0 = satt_s[lc], ws1 = satt_s[lc + 1];
            float wd0 = satt_d[lc], wd1 = satt_d[lc + 1];
            float4 a = acc[tm][tn];
            s0 += ws0 * a.x + ws1 * a.y;
            d0 += wd0 * a.x + wd1 * a.y;
            s1 += ws0 * a.z + ws1 * a.w;
            d1 += wd0 * a.z + wd1 * a.w;
            int gcol = block_col + lc;
            if (grow0 < M)
                *(__half2*)&C[(size_t)grow0 * HCn + gcol] = __floats2half2_rn(a.x, a.y);
            if (grow1 < M)
                *(__half2*)&C[(size_t)grow1 * HCn + gcol] = __floats2half2_rn(a.z, a.w);
        }
#pragma unroll
        for (int o = 1; o <= 2; o <<= 1) {
            s0 += __shfl_xor_sync(0xffffffffu, s0, o);
            s1 += __shfl_xor_sync(0xffffffffu, s1, o);
            d0 += __shfl_xor_sync(0xffffffffu, d0, o);
            d1 += __shfl_xor_sync(0xffffffffu, d1, o);
        }
        if (tig == 0) {
            if (grow0 < M) {
                atomicAdd(&asrc[grow0 * Hh + head], s0);
                atomicAdd(&adst[grow0 * Hh + head], d0);
            }
            if (grow1 < M) {
                atomicAdd(&asrc[grow1 * Hh + head], s1);
                atomicAdd(&adst[grow1 * Hh + head], d1);
            }
        }
    }
}

// ======== fused CSR aggregation + softmax + bias + ELU (fp16 gather) ========
// one warp per destination node; lane owns 8 channels (head = lane>>3).
// depth-2 software pipeline over the (csr_src -> asrc -> h-row) chain.
// CONCAT=true: writes fp16 to outh[d,256]; CONCAT=false: fp32 to outf[d,64].
template <bool CONCAT>
__global__ __launch_bounds__(256) void gat_agg_csr(
    const int* __restrict__ row_ptr, const int* __restrict__ csr_src,
    const float* __restrict__ asrc, const float* __restrict__ adst,
    const __half* __restrict__ h, const float* __restrict__ bias,
    __half* __restrict__ outh, float* __restrict__ outf, int N)
{
    __shared__ float sb[HCn];
    int tid = threadIdx.x;
    if (tid < (CONCAT ? HCn : Cc)) sb[tid] = bias[tid];
    __syncthreads();

    int d = blockIdx.x * 8 + (tid >> 5);
    int lane = tid & 31;
    if (d >= N) return;
    int head = lane >> 3;

    float adst_h = adst[d * Hh + head];
    int beg = row_ptr[d], end = row_ptr[d + 1];

    float4 acc0 = make_float4(0.f, 0.f, 0.f, 0.f);
    float4 acc1 = make_float4(0.f, 0.f, 0.f, 0.f);
    float dsum = 0.f;

    // preload slots for k=beg, beg+1 (index >= end -> self loop row d)
    int   sA = (beg < end) ? csr_src[beg] : d;
    float aA = asrc[sA * Hh + head];
    uint4 rA = *(const uint4*)&h[(size_t)sA * HCn + lane * 8];
    int   sB = (beg + 1 < end) ? csr_src[beg + 1] : d;
    float aB = asrc[sB * Hh + head];
    uint4 rB = *(const uint4*)&h[(size_t)sB * HCn + lane * 8];

    for (int k = beg; k <= end; k++) {           // k == end -> self loop
        // prefetch slot for k+2
        int   sN = (k + 2 < end) ? csr_src[k + 2] : d;
        float aN = asrc[sN * Hh + head];
        uint4 rN = *(const uint4*)&h[(size_t)sN * HCn + lane * 8];

        float p = __expf(lrelu(aA + adst_h));
        dsum += p;
        const __half2* hh = (const __half2*)&rA;
        float2 f0 = __half22float2(hh[0]);
        float2 f1 = __half22float2(hh[1]);
        float2 f2 = __half22float2(hh[2]);
        float2 f3 = __half22float2(hh[3]);
        acc0.x += p * f0.x; acc0.y += p * f0.y; acc0.z += p * f1.x; acc0.w += p * f1.y;
        acc1.x += p * f2.x; acc1.y += p * f2.y; acc1.z += p * f3.x; acc1.w += p * f3.y;

        sA = sB; aA = aB; rA = rB;
        sB = sN; aB = aN; rB = rN;
    }

    float inv = 1.f / dsum;   // identical across the 8 lanes of a head group

    if (CONCAT) {
        int c = lane * 8;
        struct { __half2 a, b, c2, d2; } pk;
        pk.a  = __floats2half2_rn(elu1(acc0.x * inv + sb[c + 0]),
                                  elu1(acc0.y * inv + sb[c + 1]));
        pk.b  = __floats2half2_rn(elu1(acc0.z * inv + sb[c + 2]),
                                  elu1(acc0.w * inv + sb[c + 3]));
        pk.c2 = __floats2half2_rn(elu1(acc1.x * inv + sb[c + 4]),
                                  elu1(acc1.y * inv + sb[c + 5]));
        pk.d2 = __floats2half2_rn(elu1(acc1.z * inv + sb[c + 6]),
                                  elu1(acc1.w * inv + sb[c + 7]));
        *(uint4*)&outh[(size_t)d * HCn + c] = *(uint4*)&pk;
    } else {
        float v[8];
        v[0] = acc0.x * inv; v[1] = acc0.y * inv; v[2] = acc0.z * inv; v[3] = acc0.w * inv;
        v[4] = acc1.x * inv; v[5] = acc1.y * inv; v[6] = acc1.z * inv; v[7] = acc1.w * inv;
#pragma unroll
        for (int j = 0; j < 8; j++) {
            v[j] += __shfl_xor_sync(0xffffffffu, v[j], 8);
            v[j] += __shfl_xor_sync(0xffffffffu, v[j], 16);
        }
        if (lane < 8) {
            int c = lane * 8;
            float4 o0, o1;
            o0.x = elu1(v[0] * 0.25f + sb[c + 0]);
            o0.y = elu1(v[1] * 0.25f + sb[c + 1]);
            o0.z = elu1(v[2] * 0.25f + sb[c + 2]);
            o0.w = elu1(v[3] * 0.25f + sb[c + 3]);
            o1.x = elu1(v[4] * 0.25f + sb[c + 4]);
            o1.y = elu1(v[5] * 0.25f + sb[c + 5]);
            o1.z = elu1(v[6] * 0.25f + sb[c + 6]);
            o1.w = elu1(v[7] * 0.25f + sb[c + 7]);
            float4* op = (float4*)&outf[(size_t)d * Cc + c];
            op[0] = o0;
            op[1] = o1;
        }
    }
}

// ---------------- pooling ----------------
__global__ void graph_bounds_k(const int* __restrict__ batch, int N,
                               int* __restrict__ start, int* __restrict__ end)
{
    int n = blockIdx.x * blockDim.x + threadIdx.x;
    if (n >= N) return;
    int g = batch[n];
    if (g < 0 || g >= NG) return;
    atomicMin(&start[g], n);
    atomicMax(&end[g], n + 1);
}

__global__ __launch_bounds__(256) void pool_k(
    const float* __restrict__ hf, const int* __restrict__ start,
    const int* __restrict__ end, float* __restrict__ pooled)
{
    int g = blockIdx.x;
    int tid = threadIdx.x;
    int col = tid & 63, sub = tid >> 6;
    int s = start[g], e = end[g];
    if (s > e) { s = 0; e = 0; }
    float acc = 0.f;
    for (int n = s + sub; n < e; n += 4) acc += hf[(size_t)n * Cc + col];
    __shared__ float sm[256];
    sm[tid] = acc;
    __syncthreads();
    if (sub == 0) {
        float v = sm[col] + sm[64 + col] + sm[128 + col] + sm[192 + col];
        float cnt = (e > s) ? (float)(e - s) : 0.f;
        pooled[g * Cc + col] = v / fmaxf(cnt, 1.0f);
    }
}

// ---------------- final head ----------------
__global__ __launch_bounds__(1024) void head_k(
    const float* __restrict__ pooled, const float* __restrict__ Wa,
    const float* __restrict__ ba, float* __restrict__ out)
{
    __shared__ float sW[Cc * NA];
    int t = threadIdx.y * 32 + threadIdx.x;
    for (int i = t; i < Cc * NA; i += 1024) sW[i] = Wa[i];
    __syncthreads();
    int a = threadIdx.x;
#pragma unroll
    for (int rep = 0; rep < 2; rep++) {
        int g = threadIdx.y + rep * 32;
        float acc = ba[a];
#pragma unroll 8
        for (int c = 0; c < Cc; c++) acc = fmaf(pooled[g * Cc + c], sW[c * NA + a], acc);
        out[g * NA + a] = acc;
    }
}

// ---------------- host orchestration ----------------
static void* symp(const void* sym) {
    void* p = nullptr;
    cudaGetSymbolAddress(&p, sym);
    return p;
}

extern "C" void kernel_launch(void* const* d_in, const int* in_sizes, int n_in,
                              void* d_out, int out_size)
{
    // -------- robust input mapping (filter size-1 scalar inputs) --------
    const void* t[13];
    int tsz[13];
    int cnt = 0;
    for (int i = 0; i < n_in && cnt < 13; i++) {
        if (in_sizes[i] <= 1) continue;
        t[cnt] = d_in[i];
        tsz[cnt] = in_sizes[i];
        cnt++;
    }
    if (cnt < 13) return;

    const float* x     = (const float*)t[0];
    const int*   ei    = (const int*)t[1];
    const int*   batch = (const int*)t[2];
    const float* W1    = (const float*)t[3];
    const float* attS1 = (const float*)t[4];
    const float* attD1 = (const float*)t[5];
    const float* b1    = (const float*)t[6];
    const float* W2    = (const float*)t[7];
    const float* attS2 = (const float*)t[8];
    const float* attD2 = (const float*)t[9];
    const float* b2    = (const float*)t[10];
    const float* Wa    = (const float*)t[11];
    const float* ba    = (const float*)t[12];

    const int Fin = 128;
    int N = tsz[0] / Fin;
    int E = tsz[1] / 2;
    if (N > MAXN || E > MAXE || N <= 0 || E <= 0) return;

    __half* ah  = (__half*)symp(g_ah);
    __half* h   = (__half*)symp(g_h);
    __half* w1t = (__half*)symp(g_w1t);
    __half* w2t = (__half*)symp(g_w2t);
    float* asrc = (float*)symp(g_asrc);
    float* adst = (float*)symp(g_adst);
    float* hf   = (float*)symp(g_hf);
    float* pooled = (float*)symp(g_pooled);
    int* gstart = (int*)symp(g_start);
    int* gend   = (int*)symp(g_end);
    int* rowptr = (int*)symp(g_rowptr);
    int* cursor = (int*)symp(g_cursor);
    int* csr    = (int*)symp(g_csr);

    // ---- pre-convert inputs to fp16 ----
    size_t n4 = (size_t)N * Fin / 4;
    convert_x_k<<<(unsigned)((n4 + 255) / 256), 256>>>(x, ah, n4);
    convert_wt_k<<<(128 * 256 + 255) / 256, 256>>>(W1, w1t, 128);
    convert_wt_k<<<(256 * 256 + 255) / 256, 256>>>(W2, w2t, 256);

    // ---- CSR build (reused by both layers) ----
    zero_deg_k<<<(N + 255) / 256, 256>>>(cursor, N);
    count_k<<<(E + 255) / 256, 256>>>(ei, E, N, cursor);
    scan_k<<<1, 1024>>>(cursor, rowptr, cursor, N);
    scatter_k<<<(E + 255) / 256, 256>>>(ei, E, N, cursor, csr);

    dim3 gemm_grid(HCn / GBN, (N + GBM - 1) / GBM);
    unsigned agg_grid = (unsigned)((N + 7) / 8);
    int nh = N * Hh;

    // ---- layer 1 ----
    zero_attn_k<<<(nh + 255) / 256, 256>>>(asrc, adst, nh);
    gemm_f16<<<gemm_grid, 256, GEMM_SMEM_BYTES>>>(ah, w1t, h, N, Fin,
                                                  attS1, attD1, asrc, adst);
    gat_agg_csr<true><<<agg_grid, 256>>>(rowptr, csr, asrc, adst, h, b1, ah, nullptr, N);

    // ---- layer 2 ----
    zero_attn_k<<<(nh + 255) / 256, 256>>>(asrc, adst, nh);
    gemm_f16<<<gemm_grid, 256, GEMM_SMEM_BYTES>>>(ah, w2t, h, N, HCn,
                                                  attS2, attD2, asrc, adst);
    gat_agg_csr<false><<<agg_grid, 256>>>(rowptr, csr, asrc, adst, h, b2, nullptr, hf, N);

    // ---- pooling ----
    init_bounds_k<<<1, 64>>>(gstart, gend);
    fill_f32<<<(NG * Cc + 255) / 256, 256>>>(pooled, NG * Cc, 0.f);
    graph_bounds_k<<<(N + 255) / 256, 256>>>(batch, N, gstart, gend);
    pool_k<<<NG, 256>>>(hf, gstart, gend, pooled);

    // ---- head ----
    head_k<<<1, dim3(32, 32)>>>(pooled, Wa, ba, (float*)d_out);
}

// round 9
// speedup vs baseline: 3.1254x; 1.0915x over previous
#include <cuda_runtime.h>
#include <cuda_fp16.h>
#include <math.h>
#include <stdio.h>
#include <stdint.h>

// ---------------- static problem capacities ----------------
#define MAXN 50000
#define MAXE 800000
#define HCn  256      // H*C
#define Hh   4
#define Cc   64
#define NG   64       // graphs
#define NA   32       // actions

// ---------------- device scratch (allocation-free rule) ----------------
__device__ __half g_ah[(size_t)MAXN * HCn];   // GEMM A input: x fp16, then h2 fp16
__device__ __half g_h [(size_t)MAXN * HCn];   // GEMM output (gather source)
__device__ __half g_w1t[256 * 128];           // W1^T fp16  [n][k]
__device__ __half g_w2t[256 * 256];           // W2^T fp16  [n][k]
__device__ float g_asrc[MAXN * Hh];
__device__ float g_adst[MAXN * Hh];
__device__ float g_hf  [(size_t)MAXN * Cc];   // final node features [N,64]
__device__ float g_pooled[NG * Cc];
__device__ int   g_start[NG];
__device__ int   g_end  [NG];
__device__ int   g_rowptr[MAXN + 1];
__device__ int   g_cursor[MAXN];
__device__ int   g_csr[MAXE];

// ---------------- helpers ----------------
__device__ __forceinline__ float lrelu(float x) { return fmaxf(x, 0.2f * x); }
__device__ __forceinline__ float elu1(float x)  { return x > 0.f ? x : expm1f(x); }

__device__ __forceinline__ void mma_f16(float4& c,
    uint32_t a0, uint32_t a1, uint32_t a2, uint32_t a3,
    uint32_t b0, uint32_t b1)
{
    asm volatile(
        "mma.sync.aligned.m16n8k16.row.col.f32.f16.f16.f32 "
        "{%0,%1,%2,%3}, {%4,%5,%6,%7}, {%8,%9}, {%0,%1,%2,%3};"
        : "+f"(c.x), "+f"(c.y), "+f"(c.z), "+f"(c.w)
        : "r"(a0), "r"(a1), "r"(a2), "r"(a3), "r"(b0), "r"(b1));
}

__device__ __forceinline__ void cp16(void* sm, const void* gm) {
    uint32_t sa = (uint32_t)__cvta_generic_to_shared(sm);
    asm volatile("cp.async.ca.shared.global [%0], [%1], 16;" :: "r"(sa), "l"(gm));
}
__device__ __forceinline__ void cp_commit() {
    asm volatile("cp.async.commit_group;" ::: "memory");
}
template <int Npend>
__device__ __forceinline__ void cp_wait() {
    asm volatile("cp.async.wait_group %0;" :: "n"(Npend) : "memory");
}

// ---------------- small utility kernels ----------------
__global__ void fill_f32(float* p, size_t n, float v) {
    size_t i = (size_t)blockIdx.x * blockDim.x + threadIdx.x;
    if (i < n) p[i] = v;
}

__global__ void zero_attn_k(float* a, float* b, int n) {
    int i = blockIdx.x * blockDim.x + threadIdx.x;
    if (i < n) { a[i] = 0.f; b[i] = 0.f; }
}

__global__ void init_bounds_k(int* start, int* end, float* pooled) {
    int i = blockIdx.x * blockDim.x + threadIdx.x;
    if (i < NG) { start[i] = 1 << 30; end[i] = 0; }
    if (i < NG * Cc) pooled[i] = 0.f;
}

// x (fp32) -> fp16, vectorized 4-wide
__global__ void convert_x_k(const float* __restrict__ x, __half* __restrict__ xh, size_t n4) {
    size_t i = (size_t)blockIdx.x * blockDim.x + threadIdx.x;
    if (i >= n4) return;
    float4 v = ((const float4*)x)[i];
    ((__half2*)xh)[i * 2]     = __floats2half2_rn(v.x, v.y);
    ((__half2*)xh)[i * 2 + 1] = __floats2half2_rn(v.z, v.w);
}

// both weights: W [K][256] fp32 -> Wt [256][K] fp16 (batched in one launch)
__global__ void convert_wt_both_k(const float* __restrict__ W1, __half* __restrict__ W1t,
                                  const float* __restrict__ W2, __half* __restrict__ W2t)
{
    int idx = blockIdx.x * blockDim.x + threadIdx.x;
    if (idx < 128 * 256) {
        int k = idx >> 8, n = idx & 255;
        W1t[n * 128 + k] = __float2half(W1[idx]);
    }
    if (idx < 256 * 256) {
        int k = idx >> 8, n = idx & 255;
        W2t[n * 256 + k] = __float2half(W2[idx]);
    }
}

// ---------------- CSR build (by destination) ----------------
__global__ void zero_deg_k(int* deg, int n) {
    int i = blockIdx.x * blockDim.x + threadIdx.x;
    if (i < n) deg[i] = 0;
}

__global__ void count_k(const int* __restrict__ ei, int E, int N, int* __restrict__ deg) {
    int i = blockIdx.x * blockDim.x + threadIdx.x;
    if (i >= E) return;
    int d = ei[E + i];
    if ((unsigned)d < (unsigned)N) atomicAdd(&deg[d], 1);
}

__global__ __launch_bounds__(1024) void scan_k(
    const int* __restrict__ deg, int* __restrict__ row_ptr,
    int* __restrict__ cursor, int N)
{
    __shared__ int part[1024];
    int t = threadIdx.x;
    int chunk = (N + 1023) / 1024;
    int b = t * chunk, e = min(b + chunk, N);
    int sum = 0;
    for (int i = b; i < e; i++) sum += deg[i];
    part[t] = sum;
    __syncthreads();
    for (int off = 1; off < 1024; off <<= 1) {
        int v = (t >= off) ? part[t - off] : 0;
        __syncthreads();
        part[t] += v;
        __syncthreads();
    }
    int run = (t > 0) ? part[t - 1] : 0;
    for (int i = b; i < e; i++) {
        row_ptr[i] = run;
        cursor[i] = run;
        run += deg[i];
    }
    if (t == 1023) row_ptr[N] = part[1023];
}

__global__ void scatter_k(const int* __restrict__ ei, int E, int N,
                          int* __restrict__ cursor, int* __restrict__ csr_src)
{
    int i = blockIdx.x * blockDim.x + threadIdx.x;
    if (i >= E) return;
    int s = ei[i];
    int d = ei[E + i];
    if ((unsigned)s >= (unsigned)N || (unsigned)d >= (unsigned)N) return;
    int pos = atomicAdd(&cursor[d], 1);
    csr_src[pos] = s;
}

// ================= fp16 tensor-core GEMM + fused attention scores ==========
#define GBM 128
#define GBN 128
#define GBK 32
#define HSTR 40                              // halfs per smem row (bank-conflict-free)
#define STAGE_H (2 * GBM * HSTR)             // halfs per stage = 10240
#define GEMM_SMEM_BYTES (2 * STAGE_H * 2)    // 40960 bytes

__device__ __forceinline__ void gemm_load_tiles(
    __half* As, __half* Bs, const __half* __restrict__ A, const __half* __restrict__ Bt,
    int M, int K, int block_row, int block_col, int k0, int tid)
{
#pragma unroll
    for (int i = 0; i < 2; i++) {
        int idx = tid * 2 + i;            // 0..511
        int r   = idx >> 2;               // 0..127
        int c   = (idx & 3) * 8;          // 0,8,16,24 (halfs)
        int gr = block_row + r;
        if (gr >= M) gr = M - 1;          // clamp: rows >= M never stored
        cp16(&As[r * HSTR + c], &A[(size_t)gr * K + k0 + c]);
    }
#pragma unroll
    for (int i = 0; i < 2; i++) {
        int idx = tid * 2 + i;
        int r   = idx >> 2;
        int c   = (idx & 3) * 8;
        cp16(&Bs[r * HSTR + c], &Bt[(size_t)(block_col + r) * K + k0 + c]);
    }
    cp_commit();
}

__global__ __launch_bounds__(256) void gemm_f16(
    const __half* __restrict__ A, const __half* __restrict__ Bt,
    __half* __restrict__ C, int M, int K,
    const float* __restrict__ att_s, const float* __restrict__ att_d,
    float* __restrict__ asrc, float* __restrict__ adst)
{
    extern __shared__ __half smem[];
    __shared__ float satt_s[GBN], satt_d[GBN];
    const int tid  = threadIdx.x;
    const int lane = tid & 31;
    const int wid  = tid >> 5;
    const int warp_m = wid & 1;
    const int warp_n = wid >> 1;
    const int gid = lane >> 2;
    const int tig = lane & 3;
    const int block_row = blockIdx.y * GBM;
    const int block_col = blockIdx.x * GBN;

    if (tid < GBN) {
        satt_s[tid] = att_s[block_col + tid];
        satt_d[tid] = att_d[block_col + tid];
    }

    float4 acc[4][4];
#pragma unroll
    for (int i = 0; i < 4; i++)
#pragma unroll
        for (int j = 0; j < 4; j++) acc[i][j] = make_float4(0.f, 0.f, 0.f, 0.f);

    const int niter = K / GBK;
    gemm_load_tiles(smem, smem + GBM * HSTR, A, Bt, M, K, block_row, block_col, 0, tid);

    for (int it = 0; it < niter; it++) {
        int cur = it & 1;
        if (it + 1 < niter) {
            __half* As_n = smem + (1 - cur) * STAGE_H;
            gemm_load_tiles(As_n, As_n + GBM * HSTR, A, Bt, M, K, block_row, block_col,
                            (it + 1) * GBK, tid);
            cp_wait<1>();
        } else {
            cp_wait<0>();
        }
        __syncthreads();

        const __half* As = smem + cur * STAGE_H;
        const __half* Bs = As + GBM * HSTR;

#pragma unroll
        for (int ks = 0; ks < 2; ks++) {        // two k16 steps per GBK=32
            int kb = ks * 16;
            uint32_t af[4][4], bf[4][2];
#pragma unroll
            for (int tm = 0; tm < 4; tm++) {
                int row = warp_m * 64 + tm * 16 + gid;
                const __half* ap = &As[row * HSTR + kb + 2 * tig];
                af[tm][0] = *(const uint32_t*)ap;
                af[tm][1] = *(const uint32_t*)(ap + 8 * HSTR);
                af[tm][2] = *(const uint32_t*)(ap + 8);
                af[tm][3] = *(const uint32_t*)(ap + 8 * HSTR + 8);
            }
#pragma unroll
            for (int tn = 0; tn < 4; tn++) {
                int col = warp_n * 32 + tn * 8 + gid;
                const __half* bp = &Bs[col * HSTR + kb + 2 * tig];
                bf[tn][0] = *(const uint32_t*)bp;
                bf[tn][1] = *(const uint32_t*)(bp + 8);
            }
#pragma unroll
            for (int tm = 0; tm < 4; tm++)
#pragma unroll
                for (int tn = 0; tn < 4; tn++)
                    mma_f16(acc[tm][tn], af[tm][0], af[tm][1], af[tm][2], af[tm][3],
                            bf[tn][0], bf[tn][1]);
        }
        __syncthreads();
    }

    const int head = (block_col + warp_n * 32) >> 6;
#pragma unroll
    for (int tm = 0; tm < 4; tm++) {
        int grow0 = block_row + warp_m * 64 + tm * 16 + gid;
        int grow1 = grow0 + 8;
        float s0 = 0.f, s1 = 0.f, d0 = 0.f, d1 = 0.f;
#pragma unroll
        for (int tn = 0; tn < 4; tn++) {
            int lc = warp_n * 32 + tn * 8 + tig * 2;
            float ws0 = satt_s[lc], ws1 = satt_s[lc + 1];
            float wd0 = satt_d[lc], wd1 = satt_d[lc + 1];
            float4 a = acc[tm][tn];
            s0 += ws0 * a.x + ws1 * a.y;
            d0 += wd0 * a.x + wd1 * a.y;
            s1 += ws0 * a.z + ws1 * a.w;
            d1 += wd0 * a.z + wd1 * a.w;
            int gcol = block_col + lc;
            if (grow0 < M)
                *(__half2*)&C[(size_t)grow0 * HCn + gcol] = __floats2half2_rn(a.x, a.y);
            if (grow1 < M)
                *(__half2*)&C[(size_t)grow1 * HCn + gcol] = __floats2half2_rn(a.z, a.w);
        }
#pragma unroll
        for (int o = 1; o <= 2; o <<= 1) {
            s0 += __shfl_xor_sync(0xffffffffu, s0, o);
            s1 += __shfl_xor_sync(0xffffffffu, s1, o);
            d0 += __shfl_xor_sync(0xffffffffu, d0, o);
            d1 += __shfl_xor_sync(0xffffffffu, d1, o);
        }
        if (tig == 0) {
            if (grow0 < M) {
                atomicAdd(&asrc[grow0 * Hh + head], s0);
                atomicAdd(&adst[grow0 * Hh + head], d0);
            }
            if (grow1 < M) {
                atomicAdd(&asrc[grow1 * Hh + head], s1);
                atomicAdd(&adst[grow1 * Hh + head], d1);
            }
        }
    }
}

// ======== fused CSR aggregation + softmax + bias + ELU (fp16 gather) ========
template <bool CONCAT>
__global__ __launch_bounds__(256) void gat_agg_csr(
    const int* __restrict__ row_ptr, const int* __restrict__ csr_src,
    const float* __restrict__ asrc, const float* __restrict__ adst,
    const __half* __restrict__ h, const float* __restrict__ bias,
    __half* __restrict__ outh, float* __restrict__ outf, int N)
{
    __shared__ float sb[HCn];
    int tid = threadIdx.x;
    if (tid < (CONCAT ? HCn : Cc)) sb[tid] = bias[tid];
    __syncthreads();

    int d = blockIdx.x * 8 + (tid >> 5);
    int lane = tid & 31;
    if (d >= N) return;
    int head = lane >> 3;

    float adst_h = adst[d * Hh + head];
    int beg = row_ptr[d], end = row_ptr[d + 1];

    float4 acc0 = make_float4(0.f, 0.f, 0.f, 0.f);
    float4 acc1 = make_float4(0.f, 0.f, 0.f, 0.f);
    float dsum = 0.f;

    int   sA = (beg < end) ? csr_src[beg] : d;
    float aA = asrc[sA * Hh + head];
    uint4 rA = *(const uint4*)&h[(size_t)sA * HCn + lane * 8];
    int   sB = (beg + 1 < end) ? csr_src[beg + 1] : d;
    float aB = asrc[sB * Hh + head];
    uint4 rB = *(const uint4*)&h[(size_t)sB * HCn + lane * 8];

    for (int k = beg; k <= end; k++) {           // k == end -> self loop
        int   sN = (k + 2 < end) ? csr_src[k + 2] : d;
        float aN = asrc[sN * Hh + head];
        uint4 rN = *(const uint4*)&h[(size_t)sN * HCn + lane * 8];

        float p = __expf(lrelu(aA + adst_h));
        dsum += p;
        const __half2* hh = (const __half2*)&rA;
        float2 f0 = __half22float2(hh[0]);
        float2 f1 = __half22float2(hh[1]);
        float2 f2 = __half22float2(hh[2]);
        float2 f3 = __half22float2(hh[3]);
        acc0.x += p * f0.x; acc0.y += p * f0.y; acc0.z += p * f1.x; acc0.w += p * f1.y;
        acc1.x += p * f2.x; acc1.y += p * f2.y; acc1.z += p * f3.x; acc1.w += p * f3.y;

        sA = sB; aA = aB; rA = rB;
        sB = sN; aB = aN; rB = rN;
    }

    float inv = 1.f / dsum;

    if (CONCAT) {
        int c = lane * 8;
        struct { __half2 a, b, c2, d2; } pk;
        pk.a  = __floats2half2_rn(elu1(acc0.x * inv + sb[c + 0]),
                                  elu1(acc0.y * inv + sb[c + 1]));
        pk.b  = __floats2half2_rn(elu1(acc0.z * inv + sb[c + 2]),
                                  elu1(acc0.w * inv + sb[c + 3]));
        pk.c2 = __floats2half2_rn(elu1(acc1.x * inv + sb[c + 4]),
                                  elu1(acc1.y * inv + sb[c + 5]));
        pk.d2 = __floats2half2_rn(elu1(acc1.z * inv + sb[c + 6]),
                                  elu1(acc1.w * inv + sb[c + 7]));
        *(uint4*)&outh[(size_t)d * HCn + c] = *(uint4*)&pk;
    } else {
        float v[8];
        v[0] = acc0.x * inv; v[1] = acc0.y * inv; v[2] = acc0.z * inv; v[3] = acc0.w * inv;
        v[4] = acc1.x * inv; v[5] = acc1.y * inv; v[6] = acc1.z * inv; v[7] = acc1.w * inv;
#pragma unroll
        for (int j = 0; j < 8; j++) {
            v[j] += __shfl_xor_sync(0xffffffffu, v[j], 8);
            v[j] += __shfl_xor_sync(0xffffffffu, v[j], 16);
        }
        if (lane < 8) {
            int c = lane * 8;
            float4 o0, o1;
            o0.x = elu1(v[0] * 0.25f + sb[c + 0]);
            o0.y = elu1(v[1] * 0.25f + sb[c + 1]);
            o0.z = elu1(v[2] * 0.25f + sb[c + 2]);
            o0.w = elu1(v[3] * 0.25f + sb[c + 3]);
            o1.x = elu1(v[4] * 0.25f + sb[c + 4]);
            o1.y = elu1(v[5] * 0.25f + sb[c + 5]);
            o1.z = elu1(v[6] * 0.25f + sb[c + 6]);
            o1.w = elu1(v[7] * 0.25f + sb[c + 7]);
            float4* op = (float4*)&outf[(size_t)d * Cc + c];
            op[0] = o0;
            op[1] = o1;
        }
    }
}

// ---------------- pooling ----------------
__global__ void graph_bounds_k(const int* __restrict__ batch, int N,
                               int* __restrict__ start, int* __restrict__ end)
{
    int n = blockIdx.x * blockDim.x + threadIdx.x;
    if (n >= N) return;
    int g = batch[n];
    if (g < 0 || g >= NG) return;
    atomicMin(&start[g], n);
    atomicMax(&end[g], n + 1);
}

__global__ __launch_bounds__(256) void pool_k(
    const float* __restrict__ hf, const int* __restrict__ start,
    const int* __restrict__ end, float* __restrict__ pooled)
{
    int g = blockIdx.x;
    int tid = threadIdx.x;
    int col = tid & 63, sub = tid >> 6;
    int s = start[g], e = end[g];
    if (s > e) { s = 0; e = 0; }
    float acc = 0.f;
    for (int n = s + sub; n < e; n += 4) acc += hf[(size_t)n * Cc + col];
    __shared__ float sm[256];
    sm[tid] = acc;
    __syncthreads();
    if (sub == 0) {
        float v = sm[col] + sm[64 + col] + sm[128 + col] + sm[192 + col];
        float cnt = (e > s) ? (float)(e - s) : 0.f;
        pooled[g * Cc + col] = v / fmaxf(cnt, 1.0f);
    }
}

// ---------------- final head ----------------
__global__ __launch_bounds__(1024) void head_k(
    const float* __restrict__ pooled, const float* __restrict__ Wa,
    const float* __restrict__ ba, float* __restrict__ out)
{
    __shared__ float sW[Cc * NA];
    int t = threadIdx.y * 32 + threadIdx.x;
    for (int i = t; i < Cc * NA; i += 1024) sW[i] = Wa[i];
    __syncthreads();
    int a = threadIdx.x;
#pragma unroll
    for (int rep = 0; rep < 2; rep++) {
        int g = threadIdx.y + rep * 32;
        float acc = ba[a];
#pragma unroll 8
        for (int c = 0; c < Cc; c++) acc = fmaf(pooled[g * Cc + c], sW[c * NA + a], acc);
        out[g * NA + a] = acc;
    }
}

// ---------------- host orchestration ----------------
static void* symp(const void* sym) {
    void* p = nullptr;
    cudaGetSymbolAddress(&p, sym);
    return p;
}

extern "C" void kernel_launch(void* const* d_in, const int* in_sizes, int n_in,
                              void* d_out, int out_size)
{
    // one-time host-side setup (first call is the uncaptured correctness run)
    static cudaStream_t sB = nullptr;
    static cudaEvent_t evFork = nullptr, evJoin = nullptr;
    if (!sB) {
        cudaStreamCreateWithFlags(&sB, cudaStreamNonBlocking);
        cudaEventCreateWithFlags(&evFork, cudaEventDisableTiming);
        cudaEventCreateWithFlags(&evJoin, cudaEventDisableTiming);
    }

    // -------- robust input mapping (filter size-1 scalar inputs) --------
    const void* t[13];
    int tsz[13];
    int cnt = 0;
    for (int i = 0; i < n_in && cnt < 13; i++) {
        if (in_sizes[i] <= 1) continue;
        t[cnt] = d_in[i];
        tsz[cnt] = in_sizes[i];
        cnt++;
    }
    if (cnt < 13) return;

    const float* x     = (const float*)t[0];
    const int*   ei    = (const int*)t[1];
    const int*   batch = (const int*)t[2];
    const float* W1    = (const float*)t[3];
    const float* attS1 = (const float*)t[4];
    const float* attD1 = (const float*)t[5];
    const float* b1    = (const float*)t[6];
    const float* W2    = (const float*)t[7];
    const float* attS2 = (const float*)t[8];
    const float* attD2 = (const float*)t[9];
    const float* b2    = (const float*)t[10];
    const float* Wa    = (const float*)t[11];
    const float* ba    = (const float*)t[12];

    const int Fin = 128;
    int N = tsz[0] / Fin;
    int E = tsz[1] / 2;
    if (N > MAXN || E > MAXE || N <= 0 || E <= 0) return;

    __half* ah  = (__half*)symp(g_ah);
    __half* h   = (__half*)symp(g_h);
    __half* w1t = (__half*)symp(g_w1t);
    __half* w2t = (__half*)symp(g_w2t);
    float* asrc = (float*)symp(g_asrc);
    float* adst = (float*)symp(g_adst);
    float* hf   = (float*)symp(g_hf);
    float* pooled = (float*)symp(g_pooled);
    int* gstart = (int*)symp(g_start);
    int* gend   = (int*)symp(g_end);
    int* rowptr = (int*)symp(g_rowptr);
    int* cursor = (int*)symp(g_cursor);
    int* csr    = (int*)symp(g_csr);

    int nh = N * Hh;
    dim3 gemm_grid(HCn / GBN, (N + GBM - 1) / GBM);
    unsigned agg_grid = (unsigned)((N + 7) / 8);

    // ======== fork: side stream builds CSR + pooling prep ========
    cudaEventRecord(evFork, 0);
    cudaStreamWaitEvent(sB, evFork, 0);

    zero_deg_k<<<(N + 255) / 256, 256, 0, sB>>>(cursor, N);
    count_k<<<(E + 255) / 256, 256, 0, sB>>>(ei, E, N, cursor);
    scan_k<<<1, 1024, 0, sB>>>(cursor, rowptr, cursor, N);
    scatter_k<<<(E + 255) / 256, 256, 0, sB>>>(ei, E, N, cursor, csr);
    init_bounds_k<<<(NG * Cc + 255) / 256, 256, 0, sB>>>(gstart, gend, pooled);
    graph_bounds_k<<<(N + 255) / 256, 256, 0, sB>>>(batch, N, gstart, gend);
    cudaEventRecord(evJoin, sB);

    // ======== main stream: converts + layer-1 GEMM ========
    size_t n4 = (size_t)N * Fin / 4;
    convert_x_k<<<(unsigned)((n4 + 255) / 256), 256>>>(x, ah, n4);
    convert_wt_both_k<<<(256 * 256 + 255) / 256, 256>>>(W1, w1t, W2, w2t);
    zero_attn_k<<<(nh + 255) / 256, 256>>>(asrc, adst, nh);
    gemm_f16<<<gemm_grid, 256, GEMM_SMEM_BYTES>>>(ah, w1t, h, N, Fin,
                                                  attS1, attD1, asrc, adst);

    // join: aggregation needs the CSR
    cudaStreamWaitEvent(0, evJoin, 0);
    gat_agg_csr<true><<<agg_grid, 256>>>(rowptr, csr, asrc, adst, h, b1, ah, nullptr, N);

    // ---- layer 2 ----
    zero_attn_k<<<(nh + 255) / 256, 256>>>(asrc, adst, nh);
    gemm_f16<<<gemm_grid, 256, GEMM_SMEM_BYTES>>>(ah, w2t, h, N, HCn,
                                                  attS2, attD2, asrc, adst);
    gat_agg_csr<false><<<agg_grid, 256>>>(rowptr, csr, asrc, adst, h, b2, nullptr, hf, N);

    // ---- pooling + head ----
    pool_k<<<NG, 256>>>(hf, gstart, gend, pooled);
    head_k<<<1, dim3(32, 32)>>>(pooled, Wa, ba, (float*)d_out);
}